// round 12
// baseline (speedup 1.0000x reference)
#include <cuda_runtime.h>
#include <cuda_bf16.h>
#include <math.h>
#include <stdint.h>

// ---------------------------------------------------------------------------
// Problem dims
// ---------------------------------------------------------------------------
#define BATCH   8
#define IMH     448
#define IMW     448
#define CSTEM   2048
#define KSTEM   147        // 3*7*7
#define KP      192        // padded K for tensor-core stem GEMM
#define NPOS    196        // 14*14
#define NX      1568       // 8*196
#define NXT     1664       // padded cols for stem mma (13*128)
#define ND1     1664       // padded cols for d1 partials (13*128)
#define NPART   6272       // 32*196 = 49*128
#define KD1     18432      // 2048*9
#define NANCH   1614
#define NSPLIT  36         // split-K for down1 (kChunk = 512, 8 chunks of 64)
#define CAT     200

// ---------------------------------------------------------------------------
// Scratch (device globals; no runtime allocation)
// ---------------------------------------------------------------------------
__device__ uint32_t g_fhl[BATCH*CSTEM*NPOS];     // stem relu, bf16 hi|lo<<16
__device__ float g_gsum[BATCH*CSTEM];            // global pooled sums (atomic)
__device__ float g_partials[NSPLIT*128*ND1];     // split-K partials
__device__ float g_d1[BATCH*128*NPOS];
__device__ float g_d2[BATCH*128*49];
__device__ float g_d3[BATCH*128*16];
__device__ float g_scores[BATCH*NANCH];
__device__ int   g_boxi[NANCH*4];
__device__ float g_boxf[NANCH*4];
__device__ int   g_pick[32];
__device__ float g_prob[32];
__device__ float g_cropf[32*4];                  // y0f, stepy, x0f, stepx
__device__ int   g_cropi[32*4];                  // y0, x0, y1-1, x1-1
__device__ float g_pfsum[32*CSTEM];              // part pooled sums (atomic)
__device__ __nv_bfloat16 g_Whi[CSTEM*KP];        // stem weights bf16 hi [m][k]
__device__ __nv_bfloat16 g_Wlo[CSTEM*KP];        // stem weights bf16 lo
__device__ __nv_bfloat16 g_Xhi[NXT*KP];          // x im2col bf16 hi [n][k]
__device__ __nv_bfloat16 g_Xlo[NXT*KP];          // x im2col bf16 lo
__device__ __nv_bfloat16 g_Phi[NPART*KP];        // part im2col bf16 hi [n][k]
__device__ __nv_bfloat16 g_Plo[NPART*KP];        // part im2col bf16 lo
__device__ __nv_bfloat16 g_d1whi[128*KD1];       // d1w bf16 hi [m][k]
__device__ __nv_bfloat16 g_d1wlo[128*KD1];       // d1w bf16 lo

__device__ __forceinline__ float warp_red(float v) {
    #pragma unroll
    for (int o = 16; o; o >>= 1) v += __shfl_down_sync(0xffffffffu, v, o);
    return v;
}
__device__ __forceinline__ float neg_inf() { return __int_as_float(0xff800000); }

__device__ __forceinline__ uint32_t pack_hilo(float v) {
    __nv_bfloat16 h = __float2bfloat16(v);
    __nv_bfloat16 l = __float2bfloat16(v - __bfloat162float(h));
    uint16_t hu = *(uint16_t*)&h, lu = *(uint16_t*)&l;
    return (uint32_t)hu | ((uint32_t)lu << 16);
}

// bf16 mma.sync (valid on base sm_100 target)
__device__ __forceinline__ void mma_bf16(float* d, const uint32_t* a, const uint32_t* b) {
    asm volatile(
        "mma.sync.aligned.m16n8k16.row.col.f32.bf16.bf16.f32 "
        "{%0,%1,%2,%3}, {%4,%5,%6,%7}, {%8,%9}, {%0,%1,%2,%3};"
        : "+f"(d[0]), "+f"(d[1]), "+f"(d[2]), "+f"(d[3])
        : "r"(a[0]), "r"(a[1]), "r"(a[2]), "r"(a[3]), "r"(b[0]), "r"(b[1]));
}

// ---------------------------------------------------------------------------
// Prep: anchors + stem/d1 weight bf16 hi/lo + accumulator zeroing
// ---------------------------------------------------------------------------
__global__ void k_prep(const float* __restrict__ sw, const float* __restrict__ d1w) {
    int idx = blockIdx.x * 256 + threadIdx.x;

    if (idx < NANCH) {
        int a = idx;
        int setting, blk, cell, stride, size, ow;
        if (a < 1176)      { setting = 0; blk = a / 196; cell = a % 196; stride = 32;  size = 48;  ow = 14; }
        else if (a < 1470) { setting = 1; int r = a - 1176; blk = r / 49; cell = r % 49; stride = 64;  size = 96;  ow = 7; }
        else               { setting = 2; int r = a - 1470; blk = r / 16; cell = r % 16; stride = 128; size = 192; ow = 4; }
        int si = blk / 3, ai = blk % 3;
        double s;
        if (setting == 2) s = (si == 0) ? 1.0 : (si == 1) ? pow(2.0, 1.0/3.0) : pow(2.0, 2.0/3.0);
        else              s = (si == 0) ? pow(2.0, 1.0/3.0) : pow(2.0, 2.0/3.0);
        double ar = (ai == 0) ? 0.667 : (ai == 1) ? 1.0 : 1.5;
        float cyf = (float)(cell / ow) * (float)stride + (float)stride * 0.5f;
        float cxf = (float)(cell % ow) * (float)stride + (float)stride * 0.5f;
        double hh = (double)size * s / sqrt(ar);
        double ww = (double)size * s * sqrt(ar);
        double e0 = ((double)cyf - hh / 2.0) + 224.0;
        double e1 = ((double)cxf - ww / 2.0) + 224.0;
        double e2 = ((double)cyf + hh / 2.0) + 224.0;
        double e3 = ((double)cxf + ww / 2.0) + 224.0;
        int b0 = (int)e0, b1 = (int)e1, b2 = (int)e2, b3 = (int)e3;
        g_boxi[a*4+0] = b0; g_boxi[a*4+1] = b1; g_boxi[a*4+2] = b2; g_boxi[a*4+3] = b3;
        g_boxf[a*4+0] = (float)b0; g_boxf[a*4+1] = (float)b1;
        g_boxf[a*4+2] = (float)b2; g_boxf[a*4+3] = (float)b3;
    }

    if (idx < CSTEM * KP) {
        int m = idx / KP, k = idx % KP;
        float v = (k < KSTEM) ? sw[m * KSTEM + k] : 0.f;
        __nv_bfloat16 h = __float2bfloat16(v);
        g_Whi[idx] = h;
        g_Wlo[idx] = __float2bfloat16(v - __bfloat162float(h));
    }

    if (idx < 128 * KD1) {
        float v = d1w[idx];
        __nv_bfloat16 h = __float2bfloat16(v);
        g_d1whi[idx] = h;
        g_d1wlo[idx] = __float2bfloat16(v - __bfloat162float(h));
    }

    if (idx < 32 * CSTEM) g_pfsum[idx] = 0.f;
    if (idx < BATCH * CSTEM) g_gsum[idx] = 0.f;
}

// im2col of x -> bf16 hi/lo, [n][KP] layout
__global__ void k_im2col_x(const float* __restrict__ x) {
    int idx = blockIdx.x * 256 + threadIdx.x;
    if (idx >= NXT * KP) return;
    int n = idx / KP, k = idx % KP;
    float v = 0.f;
    if (n < NX && k < KSTEM) {
        int b = n / NPOS, pos = n % NPOS, oy = pos / 14, ox = pos % 14;
        int c = k / 49, rr = k % 49, dy = rr / 7, dx = rr % 7;
        int iy = oy * 32 + dy - 3, ix = ox * 32 + dx - 3;
        if (iy >= 0 && ix >= 0)
            v = x[((b * 3 + c) * IMH + iy) * IMW + ix];
    }
    __nv_bfloat16 h = __float2bfloat16(v);
    g_Xhi[idx] = h;
    g_Xlo[idx] = __float2bfloat16(v - __bfloat162float(h));
}

// ---------------------------------------------------------------------------
// Shared mma tile geometry
// ---------------------------------------------------------------------------
#define KC      64
#define SSTR    72
#define TILE_E  (128 * SSTR)
#define SM_MMA_TOTAL (4 * TILE_E * 2)        // 73728 bytes

// ---------------------------------------------------------------------------
// Stem GEMM on mma.sync bf16x3: W[2048,KP] x X^T[KP,NX]
// Epilogue: bias+relu -> g_fhl (packed) + bucketed atomic global pooling.
// ---------------------------------------------------------------------------
__global__ void __launch_bounds__(256, 2) k_stem_gemm_mma(const float* __restrict__ Bias) {
    extern __shared__ __nv_bfloat16 smb[];
    __nv_bfloat16* Ah = smb;
    __nv_bfloat16* Al = smb + TILE_E;
    __nv_bfloat16* Bh = smb + 2 * TILE_E;
    __nv_bfloat16* Bl = smb + 3 * TILE_E;

    const int tid = threadIdx.x;
    const int wid = tid >> 5, lane = tid & 31;
    const int n0 = blockIdx.x * 128, m0 = blockIdx.y * 128;
    const int wm = (wid >> 2) * 64, wn = (wid & 3) * 32;
    const int g = lane >> 2, c2 = (lane & 3) * 2;

    float acc[4][4][4];
    #pragma unroll
    for (int i = 0; i < 4; i++)
        #pragma unroll
        for (int j = 0; j < 4; j++)
            #pragma unroll
            for (int r = 0; r < 4; r++) acc[i][j][r] = 0.f;

    for (int kc = 0; kc < KP; kc += KC) {
        __syncthreads();
        for (int idx = tid; idx < 1024; idx += 256) {
            int row = idx >> 3, c8 = (idx & 7) * 8;
            int so = row * SSTR + c8;
            size_t gA = (size_t)(m0 + row) * KP + kc + c8;
            size_t gB = (size_t)(n0 + row) * KP + kc + c8;
            *(uint4*)&Ah[so] = *(const uint4*)&g_Whi[gA];
            *(uint4*)&Al[so] = *(const uint4*)&g_Wlo[gA];
            *(uint4*)&Bh[so] = *(const uint4*)&g_Xhi[gB];
            *(uint4*)&Bl[so] = *(const uint4*)&g_Xlo[gB];
        }
        __syncthreads();

        #pragma unroll
        for (int ks = 0; ks < KC; ks += 16) {
            uint32_t ahi[4][4], alo[4][4], bhi[4][2], blo[4][2];
            #pragma unroll
            for (int i = 0; i < 4; i++) {
                int row = wm + i * 16 + g;
                int o0 = row * SSTR + ks + c2;
                int o1 = (row + 8) * SSTR + ks + c2;
                ahi[i][0] = *(const uint32_t*)&Ah[o0];
                ahi[i][1] = *(const uint32_t*)&Ah[o1];
                ahi[i][2] = *(const uint32_t*)&Ah[o0 + 8];
                ahi[i][3] = *(const uint32_t*)&Ah[o1 + 8];
                alo[i][0] = *(const uint32_t*)&Al[o0];
                alo[i][1] = *(const uint32_t*)&Al[o1];
                alo[i][2] = *(const uint32_t*)&Al[o0 + 8];
                alo[i][3] = *(const uint32_t*)&Al[o1 + 8];
            }
            #pragma unroll
            for (int j = 0; j < 4; j++) {
                int col = wn + j * 8 + g;
                int o = col * SSTR + ks + c2;
                bhi[j][0] = *(const uint32_t*)&Bh[o];
                bhi[j][1] = *(const uint32_t*)&Bh[o + 8];
                blo[j][0] = *(const uint32_t*)&Bl[o];
                blo[j][1] = *(const uint32_t*)&Bl[o + 8];
            }
            #pragma unroll
            for (int i = 0; i < 4; i++)
                #pragma unroll
                for (int j = 0; j < 4; j++) {
                    mma_bf16(acc[i][j], ahi[i], bhi[j]);
                    mma_bf16(acc[i][j], ahi[i], blo[j]);
                    mma_bf16(acc[i][j], alo[i], bhi[j]);
                }
        }
    }

    // epilogue: bias+relu -> packed g_fhl, bucketed atomic pooling into g_gsum
    #pragma unroll
    for (int i = 0; i < 4; i++) {
        #pragma unroll
        for (int half = 0; half < 2; half++) {
            int m = m0 + wm + i * 16 + g + half * 8;
            float bias = Bias[m];
            int pb = -1; float sum = 0.f;
            #pragma unroll
            for (int j = 0; j < 4; j++) {
                #pragma unroll
                for (int e = 0; e < 2; e++) {
                    int n = n0 + wn + j * 8 + c2 + e;
                    if (n < NX) {
                        float v = fmaxf(acc[i][j][half * 2 + e] + bias, 0.f);
                        int b = n / NPOS, pos = n % NPOS;
                        g_fhl[((size_t)(b * CSTEM + m)) * NPOS + pos] = pack_hilo(v);
                        if (b != pb) {
                            if (pb >= 0) atomicAdd(&g_gsum[pb * CSTEM + m], sum);
                            sum = 0.f; pb = b;
                        }
                        sum += v;
                    }
                }
            }
            if (pb >= 0) atomicAdd(&g_gsum[pb * CSTEM + m], sum);
        }
    }
}

// ---------------------------------------------------------------------------
// down1 GEMM on mma.sync bf16x3 (B gathered implicitly from packed g_fhl)
// ---------------------------------------------------------------------------
__global__ void __launch_bounds__(256, 2) k_d1_gemm_mma() {
    extern __shared__ __nv_bfloat16 smb[];
    __nv_bfloat16* Ah = smb;
    __nv_bfloat16* Al = smb + TILE_E;
    __nv_bfloat16* Bh = smb + 2 * TILE_E;
    __nv_bfloat16* Bl = smb + 3 * TILE_E;

    const int tid = threadIdx.x;
    const int wid = tid >> 5, lane = tid & 31;
    const int n0 = blockIdx.x * 128;
    const int kStart = blockIdx.y * (KD1 / NSPLIT);
    const int wm = (wid >> 2) * 64, wn = (wid & 3) * 32;
    const int g = lane >> 2, c2 = (lane & 3) * 2;

    const int bcol = tid & 127;
    const int kh = tid >> 7;         // 0 or 1: which 32-k half
    const int nB = n0 + bcol;
    const bool bval = nB < NX;
    int bb = 0, boy = 0, box = 0;
    if (bval) { bb = nB / NPOS; int pos = nB % NPOS; boy = pos / 14; box = pos % 14; }

    float acc[4][4][4];
    #pragma unroll
    for (int i = 0; i < 4; i++)
        #pragma unroll
        for (int j = 0; j < 4; j++)
            #pragma unroll
            for (int r = 0; r < 4; r++) acc[i][j][r] = 0.f;

    for (int kc = 0; kc < KD1 / NSPLIT; kc += KC) {
        int k0 = kStart + kc;
        __syncthreads();
        // A: pure uint4 copies
        for (int idx = tid; idx < 1024; idx += 256) {
            int row = idx >> 3, c8 = (idx & 7) * 8;
            int so = row * SSTR + c8;
            size_t gA = (size_t)row * KD1 + k0 + c8;
            *(uint4*)&Ah[so] = *(const uint4*)&g_d1whi[gA];
            *(uint4*)&Al[so] = *(const uint4*)&g_d1wlo[gA];
        }
        // B: implicit im2col gather, 2 k per u32 store
        #pragma unroll 4
        for (int kk = kh * 32; kk < kh * 32 + 32; kk += 2) {
            int k = k0 + kk;
            int c0 = k / 9, t90 = k - 9 * c0;
            int iy0 = boy + t90 / 3 - 1, ix0 = box + (t90 - 3 * (t90 / 3)) - 1;
            uint32_t v0 = 0;
            if (bval && (unsigned)iy0 < 14u && (unsigned)ix0 < 14u)
                v0 = g_fhl[((size_t)(bb * CSTEM + c0)) * NPOS + iy0 * 14 + ix0];
            int k1 = k + 1;
            int c1 = k1 / 9, t91 = k1 - 9 * c1;
            int iy1 = boy + t91 / 3 - 1, ix1 = box + (t91 - 3 * (t91 / 3)) - 1;
            uint32_t v1 = 0;
            if (bval && (unsigned)iy1 < 14u && (unsigned)ix1 < 14u)
                v1 = g_fhl[((size_t)(bb * CSTEM + c1)) * NPOS + iy1 * 14 + ix1];
            int so = bcol * SSTR + kk;   // even offset -> u32-aligned
            *(uint32_t*)&Bh[so] = (v0 & 0xFFFFu) | ((v1 & 0xFFFFu) << 16);
            *(uint32_t*)&Bl[so] = (v0 >> 16) | (v1 & 0xFFFF0000u);
        }
        __syncthreads();

        #pragma unroll
        for (int ks = 0; ks < KC; ks += 16) {
            uint32_t ahi[4][4], alo[4][4], bhi[4][2], blo[4][2];
            #pragma unroll
            for (int i = 0; i < 4; i++) {
                int row = wm + i * 16 + g;
                int o0 = row * SSTR + ks + c2;
                int o1 = (row + 8) * SSTR + ks + c2;
                ahi[i][0] = *(const uint32_t*)&Ah[o0];
                ahi[i][1] = *(const uint32_t*)&Ah[o1];
                ahi[i][2] = *(const uint32_t*)&Ah[o0 + 8];
                ahi[i][3] = *(const uint32_t*)&Ah[o1 + 8];
                alo[i][0] = *(const uint32_t*)&Al[o0];
                alo[i][1] = *(const uint32_t*)&Al[o1];
                alo[i][2] = *(const uint32_t*)&Al[o0 + 8];
                alo[i][3] = *(const uint32_t*)&Al[o1 + 8];
            }
            #pragma unroll
            for (int j = 0; j < 4; j++) {
                int col = wn + j * 8 + g;
                int o = col * SSTR + ks + c2;
                bhi[j][0] = *(const uint32_t*)&Bh[o];
                bhi[j][1] = *(const uint32_t*)&Bh[o + 8];
                blo[j][0] = *(const uint32_t*)&Bl[o];
                blo[j][1] = *(const uint32_t*)&Bl[o + 8];
            }
            #pragma unroll
            for (int i = 0; i < 4; i++)
                #pragma unroll
                for (int j = 0; j < 4; j++) {
                    mma_bf16(acc[i][j], ahi[i], bhi[j]);
                    mma_bf16(acc[i][j], ahi[i], blo[j]);
                    mma_bf16(acc[i][j], alo[i], bhi[j]);
                }
        }
    }

    float* C = g_partials + (size_t)blockIdx.y * 128 * ND1;
    #pragma unroll
    for (int i = 0; i < 4; i++) {
        #pragma unroll
        for (int half = 0; half < 2; half++) {
            int m = wm + i * 16 + g + half * 8;
            #pragma unroll
            for (int j = 0; j < 4; j++) {
                int n = n0 + wn + j * 8 + c2;
                *(float2*)(C + (size_t)m * ND1 + n) =
                    make_float2(acc[i][j][half * 2], acc[i][j][half * 2 + 1]);
            }
        }
    }
}

// ---------------------------------------------------------------------------
// Part-stem GEMM on mma.sync bf16x3 (now 2 CTAs/SM)
// ---------------------------------------------------------------------------
__global__ void __launch_bounds__(256, 2) k_part_gemm_mma(const float* __restrict__ Bias) {
    extern __shared__ __nv_bfloat16 smb[];
    __nv_bfloat16* Ah = smb;
    __nv_bfloat16* Al = smb + TILE_E;
    __nv_bfloat16* Bh = smb + 2 * TILE_E;
    __nv_bfloat16* Bl = smb + 3 * TILE_E;

    const int tid = threadIdx.x;
    const int wid = tid >> 5, lane = tid & 31;
    const int n0 = blockIdx.x * 128, m0 = blockIdx.y * 128;
    const int wm = (wid >> 2) * 64, wn = (wid & 3) * 32;
    const int g = lane >> 2, c2 = (lane & 3) * 2;

    float acc[4][4][4];
    #pragma unroll
    for (int i = 0; i < 4; i++)
        #pragma unroll
        for (int j = 0; j < 4; j++)
            #pragma unroll
            for (int r = 0; r < 4; r++) acc[i][j][r] = 0.f;

    for (int kc = 0; kc < KP; kc += KC) {
        __syncthreads();
        for (int idx = tid; idx < 1024; idx += 256) {
            int row = idx >> 3, c8 = (idx & 7) * 8;
            int so = row * SSTR + c8;
            size_t gA = (size_t)(m0 + row) * KP + kc + c8;
            size_t gB = (size_t)(n0 + row) * KP + kc + c8;
            *(uint4*)&Ah[so] = *(const uint4*)&g_Whi[gA];
            *(uint4*)&Al[so] = *(const uint4*)&g_Wlo[gA];
            *(uint4*)&Bh[so] = *(const uint4*)&g_Phi[gB];
            *(uint4*)&Bl[so] = *(const uint4*)&g_Plo[gB];
        }
        __syncthreads();

        #pragma unroll
        for (int ks = 0; ks < KC; ks += 16) {
            uint32_t ahi[4][4], alo[4][4], bhi[4][2], blo[4][2];
            #pragma unroll
            for (int i = 0; i < 4; i++) {
                int row = wm + i * 16 + g;
                int o0 = row * SSTR + ks + c2;
                int o1 = (row + 8) * SSTR + ks + c2;
                ahi[i][0] = *(const uint32_t*)&Ah[o0];
                ahi[i][1] = *(const uint32_t*)&Ah[o1];
                ahi[i][2] = *(const uint32_t*)&Ah[o0 + 8];
                ahi[i][3] = *(const uint32_t*)&Ah[o1 + 8];
                alo[i][0] = *(const uint32_t*)&Al[o0];
                alo[i][1] = *(const uint32_t*)&Al[o1];
                alo[i][2] = *(const uint32_t*)&Al[o0 + 8];
                alo[i][3] = *(const uint32_t*)&Al[o1 + 8];
            }
            #pragma unroll
            for (int j = 0; j < 4; j++) {
                int col = wn + j * 8 + g;
                int o = col * SSTR + ks + c2;
                bhi[j][0] = *(const uint32_t*)&Bh[o];
                bhi[j][1] = *(const uint32_t*)&Bh[o + 8];
                blo[j][0] = *(const uint32_t*)&Bl[o];
                blo[j][1] = *(const uint32_t*)&Bl[o + 8];
            }
            #pragma unroll
            for (int i = 0; i < 4; i++)
                #pragma unroll
                for (int j = 0; j < 4; j++) {
                    mma_bf16(acc[i][j], ahi[i], bhi[j]);
                    mma_bf16(acc[i][j], ahi[i], blo[j]);
                    mma_bf16(acc[i][j], alo[i], bhi[j]);
                }
        }
    }

    #pragma unroll
    for (int i = 0; i < 4; i++) {
        #pragma unroll
        for (int half = 0; half < 2; half++) {
            int m = m0 + wm + i * 16 + g + half * 8;
            float bias = Bias[m];
            int pb = -1; float sum = 0.f;
            #pragma unroll
            for (int j = 0; j < 4; j++) {
                #pragma unroll
                for (int e = 0; e < 2; e++) {
                    int n = n0 + wn + j * 8 + c2 + e;
                    float v = fmaxf(acc[i][j][half * 2 + e] + bias, 0.f);
                    int p = n / NPOS;
                    if (p != pb) {
                        if (pb >= 0) atomicAdd(&g_pfsum[pb * CSTEM + m], sum);
                        sum = 0.f; pb = p;
                    }
                    sum += v;
                }
            }
            atomicAdd(&g_pfsum[pb * CSTEM + m], sum);
        }
    }
}

// ---------------------------------------------------------------------------
// Epilogues / small stages
// ---------------------------------------------------------------------------
__global__ void k_raw_logits(const float* __restrict__ fcw, const float* __restrict__ fcb,
                             float* __restrict__ out) {
    int w = blockIdx.x * 8 + (threadIdx.x >> 5);
    int lane = threadIdx.x & 31;
    if (w >= BATCH * CAT) return;
    int b = w / CAT, j = w % CAT;
    const float* gv = g_gsum + b * CSTEM;
    const float* wv = fcw + (size_t)j * CSTEM;
    float s = 0.f;
    for (int k = lane; k < CSTEM; k += 32) s += gv[k] * wv[k];
    s = warp_red(s);
    if (!lane) out[w] = s / 196.0f + fcb[j];
}

__global__ void k_reduce_d1(const float* __restrict__ d1b) {
    int idx = blockIdx.x * 256 + threadIdx.x;
    if (idx >= BATCH * 128 * NPOS) return;
    int b = idx / (128 * NPOS), r = idx % (128 * NPOS);
    int c = r / NPOS, p = r % NPOS;
    int n = b * NPOS + p;
    float s = 0.f;
    #pragma unroll
    for (int z = 0; z < NSPLIT; z++) s += g_partials[(size_t)(z * 128 + c) * ND1 + n];
    g_d1[idx] = fmaxf(s + d1b[c], 0.f);
}

__global__ void k_down2(const float* __restrict__ w2, const float* __restrict__ b2) {
    int w = blockIdx.x * 8 + (threadIdx.x >> 5);
    int lane = threadIdx.x & 31;
    if (w >= BATCH * 128 * 49) return;
    int b = w / (128 * 49), r = w % (128 * 49);
    int oc = r / 49, pos = r % 49, oy = pos / 7, ox = pos % 7;
    float s = 0.f;
    for (int ic = lane; ic < 128; ic += 32) {
        const float* dp = g_d1 + (size_t)(b * 128 + ic) * NPOS;
        const float* wp = w2 + (size_t)(oc * 128 + ic) * 9;
        #pragma unroll
        for (int ky = 0; ky < 3; ky++) {
            int iy = oy * 2 + ky - 1;
            if ((unsigned)iy >= 14u) continue;
            #pragma unroll
            for (int kx = 0; kx < 3; kx++) {
                int ix = ox * 2 + kx - 1;
                if ((unsigned)ix < 14u) s += wp[ky * 3 + kx] * dp[iy * 14 + ix];
            }
        }
    }
    s = warp_red(s);
    if (!lane) g_d2[w] = fmaxf(s + b2[oc], 0.f);
}

__global__ void k_down3(const float* __restrict__ w3, const float* __restrict__ b3) {
    int w = blockIdx.x * 8 + (threadIdx.x >> 5);
    int lane = threadIdx.x & 31;
    if (w >= BATCH * 128 * 16) return;
    int b = w / (128 * 16), r = w % (128 * 16);
    int oc = r / 16, pos = r % 16, oy = pos / 4, ox = pos % 4;
    float s = 0.f;
    for (int ic = lane; ic < 128; ic += 32) {
        const float* dp = g_d2 + (size_t)(b * 128 + ic) * 49;
        const float* wp = w3 + (size_t)(oc * 128 + ic) * 9;
        #pragma unroll
        for (int ky = 0; ky < 3; ky++) {
            int iy = oy * 2 + ky - 1;
            if ((unsigned)iy >= 7u) continue;
            #pragma unroll
            for (int kx = 0; kx < 3; kx++) {
                int ix = ox * 2 + kx - 1;
                if ((unsigned)ix < 7u) s += wp[ky * 3 + kx] * dp[iy * 7 + ix];
            }
        }
    }
    s = warp_red(s);
    if (!lane) g_d3[w] = fmaxf(s + b3[oc], 0.f);
}

__global__ void k_tidy(const float* __restrict__ w1, const float* __restrict__ b1,
                       const float* __restrict__ w2, const float* __restrict__ b2,
                       const float* __restrict__ w3, const float* __restrict__ b3) {
    int w = blockIdx.x * 8 + (threadIdx.x >> 5);
    int lane = threadIdx.x & 31;
    if (w >= BATCH * NANCH) return;
    int b = w / NANCH, o = w % NANCH;
    const float* src; const float* wt; float bias; int S;
    if (o < 1176)      { int oc = o / 196, pos = o % 196; src = g_d1 + (size_t)b * 128 * 196 + pos; S = 196; wt = w1 + oc * 128; bias = b1[oc]; }
    else if (o < 1470) { int r = o - 1176, oc = r / 49, pos = r % 49; src = g_d2 + (size_t)b * 128 * 49 + pos; S = 49; wt = w2 + oc * 128; bias = b2[oc]; }
    else               { int r = o - 1470, oc = r / 16, pos = r % 16; src = g_d3 + (size_t)b * 128 * 16 + pos; S = 16; wt = w3 + oc * 128; bias = b3[oc]; }
    float s = 0.f;
    for (int ic = lane; ic < 128; ic += 32) s += wt[ic] * src[ic * S];
    s = warp_red(s);
    if (!lane) g_scores[b * NANCH + o] = s + bias;
}

// ---------------------------------------------------------------------------
// NMS (one block per image, matches jnp.argmax first-max tie-break)
// ---------------------------------------------------------------------------
__global__ void k_nms() {
    __shared__ float sm[NANCH];
    __shared__ float rv[256];
    __shared__ int   ri[256];
    int b = blockIdx.x, tid = threadIdx.x;
    for (int i = tid; i < NANCH; i += 256) sm[i] = g_scores[b * NANCH + i];
    __syncthreads();
    for (int t = 0; t < 4; t++) {
        float bv = neg_inf(); int bi = 0x3fffffff;
        for (int i = tid; i < NANCH; i += 256) {
            float v = sm[i];
            if (v > bv || (v == bv && i < bi)) { bv = v; bi = i; }
        }
        rv[tid] = bv; ri[tid] = bi;
        __syncthreads();
        for (int s = 128; s > 0; s >>= 1) {
            if (tid < s) {
                float v2 = rv[tid + s]; int i2 = ri[tid + s];
                if (v2 > rv[tid] || (v2 == rv[tid] && i2 < ri[tid])) { rv[tid] = v2; ri[tid] = i2; }
            }
            __syncthreads();
        }
        int pick = ri[0];
        if (tid == 0) {
            g_pick[b * 4 + t] = pick;
            g_prob[b * 4 + t] = g_scores[b * NANCH + pick];
            int y0 = g_boxi[pick * 4 + 0], x0 = g_boxi[pick * 4 + 1];
            int y1 = max(g_boxi[pick * 4 + 2], y0 + 1);
            int x1 = max(g_boxi[pick * 4 + 3], x0 + 1);
            int pi = b * 4 + t;
            g_cropi[pi * 4 + 0] = y0; g_cropi[pi * 4 + 1] = x0;
            g_cropi[pi * 4 + 2] = y1 - 1; g_cropi[pi * 4 + 3] = x1 - 1;
            g_cropf[pi * 4 + 0] = (float)y0;
            g_cropf[pi * 4 + 1] = __fdiv_rn((float)(y1 - 1 - y0), 447.0f);
            g_cropf[pi * 4 + 2] = (float)x0;
            g_cropf[pi * 4 + 3] = __fdiv_rn((float)(x1 - 1 - x0), 447.0f);
        }
        __syncthreads();
        float py0 = g_boxf[pick * 4], px0 = g_boxf[pick * 4 + 1];
        float py1 = g_boxf[pick * 4 + 2], px1 = g_boxf[pick * 4 + 3];
        float pa = (py1 - py0) * (px1 - px0);
        for (int i = tid; i < NANCH; i += 256) {
            float qy0 = g_boxf[i * 4], qx0 = g_boxf[i * 4 + 1];
            float qy1 = g_boxf[i * 4 + 2], qx1 = g_boxf[i * 4 + 3];
            float t0 = fmaxf(qy0, py0), t1 = fmaxf(qx0, px0);
            float bb0 = fminf(qy1, py1), bb1 = fminf(qx1, px1);
            float w0 = bb0 - t0, w1 = bb1 - t1;
            float inter = (w0 < 0.f || w1 < 0.f) ? 0.f : w0 * w1;
            float qa = (qy1 - qy0) * (qx1 - qx0);
            float iou = inter / (qa + pa - inter);
            if (!(iou < 0.25f)) sm[i] = neg_inf();
        }
        __syncthreads();
    }
}

// ---------------------------------------------------------------------------
// Fused crop-resize + im2col for part stem -> bf16 hi/lo [n][KP]
// ---------------------------------------------------------------------------
__global__ void k_part_im2col(const float* __restrict__ x) {
    int idx = blockIdx.x * 256 + threadIdx.x;
    if (idx >= NPART * KP) return;
    int col = idx / KP, r = idx % KP;
    float v = 0.f;
    if (r < KSTEM) {
        int p = col / NPOS, pos = col % NPOS, oy = pos / 14, ox = pos % 14;
        int c = r / 49, rr = r % 49, dy = rr / 7, dx = rr % 7;
        int iy = oy * 32 + dy - 3, ix = ox * 32 + dx - 3;
        if (iy >= 0 && ix >= 0) {
            int b = p >> 2;
            float y0f = g_cropf[p * 4 + 0], sy = g_cropf[p * 4 + 1];
            float x0f = g_cropf[p * 4 + 2], sx = g_cropf[p * 4 + 3];
            int y1m1 = g_cropi[p * 4 + 2], x1m1 = g_cropi[p * 4 + 3];
            float fy = __fadd_rn(y0f, __fmul_rn((float)iy, sy));
            int yl = (int)floorf(fy);
            float wy = __fsub_rn(fy, (float)yl);
            int yh = min(yl + 1, y1m1);
            float fx = __fadd_rn(x0f, __fmul_rn((float)ix, sx));
            int xl = (int)floorf(fx);
            float wx = __fsub_rn(fx, (float)xl);
            int xh = min(xl + 1, x1m1);
            const float* xb = x + (size_t)(b * 3 + c) * IMH * IMW;
            int ry0 = yl - 224, ry1 = yh - 224, rx0 = xl - 224, rx1 = xh - 224;
            float vll = ((unsigned)ry0 < 448u && (unsigned)rx0 < 448u) ? xb[ry0 * IMW + rx0] : 0.f;
            float vlh = ((unsigned)ry0 < 448u && (unsigned)rx1 < 448u) ? xb[ry0 * IMW + rx1] : 0.f;
            float vhl = ((unsigned)ry1 < 448u && (unsigned)rx0 < 448u) ? xb[ry1 * IMW + rx0] : 0.f;
            float vhh = ((unsigned)ry1 < 448u && (unsigned)rx1 < 448u) ? xb[ry1 * IMW + rx1] : 0.f;
            float omy = __fsub_rn(1.f, wy), omx = __fsub_rn(1.f, wx);
            float top = __fadd_rn(__fmul_rn(omx, vll), __fmul_rn(wx, vlh));
            float bot = __fadd_rn(__fmul_rn(omx, vhl), __fmul_rn(wx, vhh));
            v = __fadd_rn(__fmul_rn(omy, top), __fmul_rn(wy, bot));
        }
    }
    __nv_bfloat16 h = __float2bfloat16(v);
    g_Phi[idx] = h;
    g_Plo[idx] = __float2bfloat16(v - __bfloat162float(h));
}

__global__ void k_fc_concat(const float* __restrict__ cw, const float* __restrict__ cb,
                            float* __restrict__ out) {
    int w = blockIdx.x * 8 + (threadIdx.x >> 5);
    int lane = threadIdx.x & 31;
    if (w >= BATCH * CAT) return;
    int b = w / CAT, j = w % CAT;
    const float* wv = cw + (size_t)j * 10240;
    const float* pfs = g_pfsum + (size_t)b * 4 * CSTEM;
    float s = 0.f;
    for (int k = lane; k < 8192; k += 32) s += pfs[k] * wv[k];
    const float* gv = g_gsum + b * CSTEM;
    for (int k = lane; k < 2048; k += 32) s += gv[k] * wv[8192 + k];
    s = warp_red(s);
    if (!lane) out[1600 + w] = s / 196.0f + cb[j];
}

__global__ void k_fc_part(const float* __restrict__ pw, const float* __restrict__ pb,
                          float* __restrict__ out) {
    int w = blockIdx.x * 8 + (threadIdx.x >> 5);
    int lane = threadIdx.x & 31;
    if (w >= 32 * CAT) return;
    int p = w / CAT, j = w % CAT;
    const float* av = g_pfsum + (size_t)p * CSTEM;
    const float* wv = pw + (size_t)j * CSTEM;
    float s = 0.f;
    for (int k = lane; k < CSTEM; k += 32) s += av[k] * wv[k];
    s = warp_red(s / 196.0f);
    if (!lane) out[3200 + w] = s + pb[j];
}

__global__ void k_tail(float* __restrict__ out) {
    int i = threadIdx.x;
    if (i < 32) {
        out[9600 + i] = (float)g_pick[i];
        out[9632 + i] = g_prob[i];
    }
}

// ---------------------------------------------------------------------------
// Launch
// ---------------------------------------------------------------------------
extern "C" void kernel_launch(void* const* d_in, const int* in_sizes, int n_in,
                              void* d_out, int out_size) {
    (void)in_sizes; (void)n_in; (void)out_size;
    const float* x      = (const float*)d_in[0];
    const float* stem_w = (const float*)d_in[1];
    const float* stem_b = (const float*)d_in[2];
    const float* fc_w   = (const float*)d_in[3];
    const float* fc_b   = (const float*)d_in[4];
    const float* d1w    = (const float*)d_in[5];
    const float* d1b    = (const float*)d_in[6];
    const float* d2w    = (const float*)d_in[7];
    const float* d2b    = (const float*)d_in[8];
    const float* d3w    = (const float*)d_in[9];
    const float* d3b    = (const float*)d_in[10];
    const float* t1w    = (const float*)d_in[11];
    const float* t1b    = (const float*)d_in[12];
    const float* t2w    = (const float*)d_in[13];
    const float* t2b    = (const float*)d_in[14];
    const float* t3w    = (const float*)d_in[15];
    const float* t3b    = (const float*)d_in[16];
    const float* cw     = (const float*)d_in[17];
    const float* cb     = (const float*)d_in[18];
    const float* pw     = (const float*)d_in[19];
    const float* pb     = (const float*)d_in[20];
    float* out = (float*)d_out;

    cudaFuncSetAttribute(k_stem_gemm_mma, cudaFuncAttributeMaxDynamicSharedMemorySize,
                         SM_MMA_TOTAL);
    cudaFuncSetAttribute(k_d1_gemm_mma, cudaFuncAttributeMaxDynamicSharedMemorySize,
                         SM_MMA_TOTAL);
    cudaFuncSetAttribute(k_part_gemm_mma, cudaFuncAttributeMaxDynamicSharedMemorySize,
                         SM_MMA_TOTAL);

    // prep: anchors + weight hi/lo splits + accumulator zeroing
    k_prep<<<(128 * KD1 + 255) / 256, 256>>>(stem_w, d1w);

    // --- backbone on x: tensor-core stem GEMM (fused relu+pack+pool) ---
    k_im2col_x<<<(NXT * KP + 255) / 256, 256>>>(x);
    k_stem_gemm_mma<<<dim3(NXT / 128, CSTEM / 128), 256, SM_MMA_TOTAL>>>(stem_b);
    k_raw_logits<<<(BATCH * CAT) / 8, 256>>>(fc_w, fc_b, out);

    // --- proposal net: tensor-core d1 GEMM (implicit im2col gather) ---
    k_d1_gemm_mma<<<dim3(ND1 / 128, NSPLIT), 256, SM_MMA_TOTAL>>>();
    k_reduce_d1<<<(BATCH * 128 * NPOS + 255) / 256, 256>>>(d1b);
    k_down2<<<(BATCH * 128 * 49 + 7) / 8, 256>>>(d2w, d2b);
    k_down3<<<(BATCH * 128 * 16 + 7) / 8, 256>>>(d3w, d3b);
    k_tidy<<<(BATCH * NANCH + 7) / 8, 256>>>(t1w, t1b, t2w, t2b, t3w, t3b);

    // --- NMS ---
    k_nms<<<8, 256>>>();

    // --- part branch: crop-resize im2col (bf16 hi/lo) + mma.sync GEMM ---
    k_part_im2col<<<(NPART * KP + 255) / 256, 256>>>(x);
    k_part_gemm_mma<<<dim3(NPART / 128, CSTEM / 128), 256, SM_MMA_TOTAL>>>(stem_b);

    // --- heads ---
    k_fc_concat<<<(BATCH * CAT) / 8, 256>>>(cw, cb, out);
    k_fc_part<<<(32 * CAT) / 8, 256>>>(pw, pb, out);
    k_tail<<<1, 64>>>(out);
}

// round 13
// speedup vs baseline: 1.0208x; 1.0208x over previous
#include <cuda_runtime.h>
#include <cuda_bf16.h>
#include <math.h>
#include <stdint.h>

// ---------------------------------------------------------------------------
// Problem dims
// ---------------------------------------------------------------------------
#define BATCH   8
#define IMH     448
#define IMW     448
#define CSTEM   2048
#define KSTEM   147        // 3*7*7
#define KP      192        // padded K for tensor-core stem GEMM
#define NPOS    196        // 14*14
#define NX      1568       // 8*196
#define NXT     1664       // padded cols for stem mma (13*128)
#define ND1     1664       // padded cols for d1 partials (13*128)
#define NPART   6272       // 32*196 = 49*128
#define KD1     18432      // 2048*9
#define NANCH   1614
#define NSPLIT  32         // split-K for down1 (kChunk = 576)
#define CAT     200

// ---------------------------------------------------------------------------
// Scratch (device globals; no runtime allocation)
// ---------------------------------------------------------------------------
__device__ uint32_t g_fhl[BATCH*CSTEM*NPOS];     // stem relu, bf16 hi|lo<<16
__device__ float g_gsum[BATCH*CSTEM];            // global pooled sums (atomic)
__device__ float g_partials[NSPLIT*128*ND1];     // split-K partials
__device__ float g_d1[BATCH*128*NPOS];
__device__ float g_d2[BATCH*128*49];
__device__ float g_d3[BATCH*128*16];
__device__ float g_scores[BATCH*NANCH];
__device__ int   g_boxi[NANCH*4];
__device__ float g_boxf[NANCH*4];
__device__ int   g_pick[32];
__device__ float g_prob[32];
__device__ float g_cropf[32*4];                  // y0f, stepy, x0f, stepx
__device__ int   g_cropi[32*4];                  // y0, x0, y1-1, x1-1
__device__ float g_pfsum[32*CSTEM];              // part pooled sums (atomic)
__device__ __nv_bfloat16 g_Whi[CSTEM*KP];        // stem weights bf16 hi [m][k]
__device__ __nv_bfloat16 g_Wlo[CSTEM*KP];        // stem weights bf16 lo
__device__ __nv_bfloat16 g_Xhi[NXT*KP];          // x im2col bf16 hi [n][k]
__device__ __nv_bfloat16 g_Xlo[NXT*KP];          // x im2col bf16 lo
__device__ __nv_bfloat16 g_Phi[NPART*KP];        // part im2col bf16 hi [n][k]
__device__ __nv_bfloat16 g_Plo[NPART*KP];        // part im2col bf16 lo
__device__ __nv_bfloat16 g_d1whi[128*KD1];       // d1w bf16 hi [m][k]
__device__ __nv_bfloat16 g_d1wlo[128*KD1];       // d1w bf16 lo

__device__ __forceinline__ float warp_red(float v) {
    #pragma unroll
    for (int o = 16; o; o >>= 1) v += __shfl_down_sync(0xffffffffu, v, o);
    return v;
}
__device__ __forceinline__ float neg_inf() { return __int_as_float(0xff800000); }

__device__ __forceinline__ uint32_t pack_hilo(float v) {
    __nv_bfloat16 h = __float2bfloat16(v);
    __nv_bfloat16 l = __float2bfloat16(v - __bfloat162float(h));
    uint16_t hu = *(uint16_t*)&h, lu = *(uint16_t*)&l;
    return (uint32_t)hu | ((uint32_t)lu << 16);
}

// bf16 mma.sync (valid on base sm_100 target)
__device__ __forceinline__ void mma_bf16(float* d, const uint32_t* a, const uint32_t* b) {
    asm volatile(
        "mma.sync.aligned.m16n8k16.row.col.f32.bf16.bf16.f32 "
        "{%0,%1,%2,%3}, {%4,%5,%6,%7}, {%8,%9}, {%0,%1,%2,%3};"
        : "+f"(d[0]), "+f"(d[1]), "+f"(d[2]), "+f"(d[3])
        : "r"(a[0]), "r"(a[1]), "r"(a[2]), "r"(a[3]), "r"(b[0]), "r"(b[1]));
}

// ---------------------------------------------------------------------------
// Prep: anchors + stem/d1 weight bf16 hi/lo + accumulator zeroing
// ---------------------------------------------------------------------------
__global__ void k_prep(const float* __restrict__ sw, const float* __restrict__ d1w) {
    int idx = blockIdx.x * 256 + threadIdx.x;

    if (idx < NANCH) {
        int a = idx;
        int setting, blk, cell, stride, size, ow;
        if (a < 1176)      { setting = 0; blk = a / 196; cell = a % 196; stride = 32;  size = 48;  ow = 14; }
        else if (a < 1470) { setting = 1; int r = a - 1176; blk = r / 49; cell = r % 49; stride = 64;  size = 96;  ow = 7; }
        else               { setting = 2; int r = a - 1470; blk = r / 16; cell = r % 16; stride = 128; size = 192; ow = 4; }
        int si = blk / 3, ai = blk % 3;
        double s;
        if (setting == 2) s = (si == 0) ? 1.0 : (si == 1) ? pow(2.0, 1.0/3.0) : pow(2.0, 2.0/3.0);
        else              s = (si == 0) ? pow(2.0, 1.0/3.0) : pow(2.0, 2.0/3.0);
        double ar = (ai == 0) ? 0.667 : (ai == 1) ? 1.0 : 1.5;
        float cyf = (float)(cell / ow) * (float)stride + (float)stride * 0.5f;
        float cxf = (float)(cell % ow) * (float)stride + (float)stride * 0.5f;
        double hh = (double)size * s / sqrt(ar);
        double ww = (double)size * s * sqrt(ar);
        double e0 = ((double)cyf - hh / 2.0) + 224.0;
        double e1 = ((double)cxf - ww / 2.0) + 224.0;
        double e2 = ((double)cyf + hh / 2.0) + 224.0;
        double e3 = ((double)cxf + ww / 2.0) + 224.0;
        int b0 = (int)e0, b1 = (int)e1, b2 = (int)e2, b3 = (int)e3;
        g_boxi[a*4+0] = b0; g_boxi[a*4+1] = b1; g_boxi[a*4+2] = b2; g_boxi[a*4+3] = b3;
        g_boxf[a*4+0] = (float)b0; g_boxf[a*4+1] = (float)b1;
        g_boxf[a*4+2] = (float)b2; g_boxf[a*4+3] = (float)b3;
    }

    if (idx < CSTEM * KP) {
        int m = idx / KP, k = idx % KP;
        float v = (k < KSTEM) ? sw[m * KSTEM + k] : 0.f;
        __nv_bfloat16 h = __float2bfloat16(v);
        g_Whi[idx] = h;
        g_Wlo[idx] = __float2bfloat16(v - __bfloat162float(h));
    }

    if (idx < 128 * KD1) {
        float v = d1w[idx];
        __nv_bfloat16 h = __float2bfloat16(v);
        g_d1whi[idx] = h;
        g_d1wlo[idx] = __float2bfloat16(v - __bfloat162float(h));
    }

    if (idx < 32 * CSTEM) g_pfsum[idx] = 0.f;
    if (idx < BATCH * CSTEM) g_gsum[idx] = 0.f;
}

// im2col of x -> bf16 hi/lo, [n][KP] layout
__global__ void k_im2col_x(const float* __restrict__ x) {
    int idx = blockIdx.x * 256 + threadIdx.x;
    if (idx >= NXT * KP) return;
    int n = idx / KP, k = idx % KP;
    float v = 0.f;
    if (n < NX && k < KSTEM) {
        int b = n / NPOS, pos = n % NPOS, oy = pos / 14, ox = pos % 14;
        int c = k / 49, rr = k % 49, dy = rr / 7, dx = rr % 7;
        int iy = oy * 32 + dy - 3, ix = ox * 32 + dx - 3;
        if (iy >= 0 && ix >= 0)
            v = x[((b * 3 + c) * IMH + iy) * IMW + ix];
    }
    __nv_bfloat16 h = __float2bfloat16(v);
    g_Xhi[idx] = h;
    g_Xlo[idx] = __float2bfloat16(v - __bfloat162float(h));
}

// ---------------------------------------------------------------------------
// Shared mma tile geometry
// ---------------------------------------------------------------------------
#define KC      64
#define SSTR    72
#define TILE_E  (128 * SSTR)
#define SM_MMA_TOTAL (4 * TILE_E * 2)        // 73728 bytes

// ---------------------------------------------------------------------------
// Stem GEMM on mma.sync bf16x3: W[2048,KP] x X^T[KP,NX]
// Epilogue: bias+relu -> g_fhl (packed) + bucketed atomic global pooling.
// ---------------------------------------------------------------------------
__global__ void __launch_bounds__(256, 2) k_stem_gemm_mma(const float* __restrict__ Bias) {
    extern __shared__ __nv_bfloat16 smb[];
    __nv_bfloat16* Ah = smb;
    __nv_bfloat16* Al = smb + TILE_E;
    __nv_bfloat16* Bh = smb + 2 * TILE_E;
    __nv_bfloat16* Bl = smb + 3 * TILE_E;

    const int tid = threadIdx.x;
    const int wid = tid >> 5, lane = tid & 31;
    const int n0 = blockIdx.x * 128, m0 = blockIdx.y * 128;
    const int wm = (wid >> 2) * 64, wn = (wid & 3) * 32;
    const int g = lane >> 2, c2 = (lane & 3) * 2;

    float acc[4][4][4];
    #pragma unroll
    for (int i = 0; i < 4; i++)
        #pragma unroll
        for (int j = 0; j < 4; j++)
            #pragma unroll
            for (int r = 0; r < 4; r++) acc[i][j][r] = 0.f;

    for (int kc = 0; kc < KP; kc += KC) {
        __syncthreads();
        for (int idx = tid; idx < 1024; idx += 256) {
            int row = idx >> 3, c8 = (idx & 7) * 8;
            int so = row * SSTR + c8;
            size_t gA = (size_t)(m0 + row) * KP + kc + c8;
            size_t gB = (size_t)(n0 + row) * KP + kc + c8;
            *(uint4*)&Ah[so] = *(const uint4*)&g_Whi[gA];
            *(uint4*)&Al[so] = *(const uint4*)&g_Wlo[gA];
            *(uint4*)&Bh[so] = *(const uint4*)&g_Xhi[gB];
            *(uint4*)&Bl[so] = *(const uint4*)&g_Xlo[gB];
        }
        __syncthreads();

        #pragma unroll
        for (int ks = 0; ks < KC; ks += 16) {
            uint32_t ahi[4][4], alo[4][4], bhi[4][2], blo[4][2];
            #pragma unroll
            for (int i = 0; i < 4; i++) {
                int row = wm + i * 16 + g;
                int o0 = row * SSTR + ks + c2;
                int o1 = (row + 8) * SSTR + ks + c2;
                ahi[i][0] = *(const uint32_t*)&Ah[o0];
                ahi[i][1] = *(const uint32_t*)&Ah[o1];
                ahi[i][2] = *(const uint32_t*)&Ah[o0 + 8];
                ahi[i][3] = *(const uint32_t*)&Ah[o1 + 8];
                alo[i][0] = *(const uint32_t*)&Al[o0];
                alo[i][1] = *(const uint32_t*)&Al[o1];
                alo[i][2] = *(const uint32_t*)&Al[o0 + 8];
                alo[i][3] = *(const uint32_t*)&Al[o1 + 8];
            }
            #pragma unroll
            for (int j = 0; j < 4; j++) {
                int col = wn + j * 8 + g;
                int o = col * SSTR + ks + c2;
                bhi[j][0] = *(const uint32_t*)&Bh[o];
                bhi[j][1] = *(const uint32_t*)&Bh[o + 8];
                blo[j][0] = *(const uint32_t*)&Bl[o];
                blo[j][1] = *(const uint32_t*)&Bl[o + 8];
            }
            #pragma unroll
            for (int i = 0; i < 4; i++)
                #pragma unroll
                for (int j = 0; j < 4; j++) {
                    mma_bf16(acc[i][j], ahi[i], bhi[j]);
                    mma_bf16(acc[i][j], ahi[i], blo[j]);
                    mma_bf16(acc[i][j], alo[i], bhi[j]);
                }
        }
    }

    // epilogue: bias+relu -> packed g_fhl, bucketed atomic pooling into g_gsum
    #pragma unroll
    for (int i = 0; i < 4; i++) {
        #pragma unroll
        for (int half = 0; half < 2; half++) {
            int m = m0 + wm + i * 16 + g + half * 8;
            float bias = Bias[m];
            int pb = -1; float sum = 0.f;
            #pragma unroll
            for (int j = 0; j < 4; j++) {
                #pragma unroll
                for (int e = 0; e < 2; e++) {
                    int n = n0 + wn + j * 8 + c2 + e;
                    if (n < NX) {
                        float v = fmaxf(acc[i][j][half * 2 + e] + bias, 0.f);
                        int b = n / NPOS, pos = n % NPOS;
                        g_fhl[((size_t)(b * CSTEM + m)) * NPOS + pos] = pack_hilo(v);
                        if (b != pb) {
                            if (pb >= 0) atomicAdd(&g_gsum[pb * CSTEM + m], sum);
                            sum = 0.f; pb = b;
                        }
                        sum += v;
                    }
                }
            }
            if (pb >= 0) atomicAdd(&g_gsum[pb * CSTEM + m], sum);
        }
    }
}

// ---------------------------------------------------------------------------
// down1 GEMM on mma.sync bf16x3 (B gathered implicitly from packed g_fhl)
// ---------------------------------------------------------------------------
__global__ void __launch_bounds__(256, 2) k_d1_gemm_mma() {
    extern __shared__ __nv_bfloat16 smb[];
    __nv_bfloat16* Ah = smb;
    __nv_bfloat16* Al = smb + TILE_E;
    __nv_bfloat16* Bh = smb + 2 * TILE_E;
    __nv_bfloat16* Bl = smb + 3 * TILE_E;

    const int tid = threadIdx.x;
    const int wid = tid >> 5, lane = tid & 31;
    const int n0 = blockIdx.x * 128;
    const int kStart = blockIdx.y * (KD1 / NSPLIT);
    const int wm = (wid >> 2) * 64, wn = (wid & 3) * 32;
    const int g = lane >> 2, c2 = (lane & 3) * 2;

    const int bcol = tid & 127;
    const int kh = tid >> 7;         // 0 or 1: which 32-k half
    const int nB = n0 + bcol;
    const bool bval = nB < NX;
    int bb = 0, boy = 0, box = 0;
    if (bval) { bb = nB / NPOS; int pos = nB % NPOS; boy = pos / 14; box = pos % 14; }

    float acc[4][4][4];
    #pragma unroll
    for (int i = 0; i < 4; i++)
        #pragma unroll
        for (int j = 0; j < 4; j++)
            #pragma unroll
            for (int r = 0; r < 4; r++) acc[i][j][r] = 0.f;

    for (int kc = 0; kc < KD1 / NSPLIT; kc += KC) {
        int k0 = kStart + kc;
        __syncthreads();
        // A: pure uint4 copies
        for (int idx = tid; idx < 1024; idx += 256) {
            int row = idx >> 3, c8 = (idx & 7) * 8;
            int so = row * SSTR + c8;
            size_t gA = (size_t)row * KD1 + k0 + c8;
            *(uint4*)&Ah[so] = *(const uint4*)&g_d1whi[gA];
            *(uint4*)&Al[so] = *(const uint4*)&g_d1wlo[gA];
        }
        // B: implicit im2col gather, 2 k per u32 store
        #pragma unroll 4
        for (int kk = kh * 32; kk < kh * 32 + 32; kk += 2) {
            int k = k0 + kk;
            int c0 = k / 9, t90 = k - 9 * c0;
            int iy0 = boy + t90 / 3 - 1, ix0 = box + (t90 - 3 * (t90 / 3)) - 1;
            uint32_t v0 = 0;
            if (bval && (unsigned)iy0 < 14u && (unsigned)ix0 < 14u)
                v0 = g_fhl[((size_t)(bb * CSTEM + c0)) * NPOS + iy0 * 14 + ix0];
            int k1 = k + 1;
            int c1 = k1 / 9, t91 = k1 - 9 * c1;
            int iy1 = boy + t91 / 3 - 1, ix1 = box + (t91 - 3 * (t91 / 3)) - 1;
            uint32_t v1 = 0;
            if (bval && (unsigned)iy1 < 14u && (unsigned)ix1 < 14u)
                v1 = g_fhl[((size_t)(bb * CSTEM + c1)) * NPOS + iy1 * 14 + ix1];
            int so = bcol * SSTR + kk;   // even offset -> u32-aligned
            *(uint32_t*)&Bh[so] = (v0 & 0xFFFFu) | ((v1 & 0xFFFFu) << 16);
            *(uint32_t*)&Bl[so] = (v0 >> 16) | (v1 & 0xFFFF0000u);
        }
        __syncthreads();

        #pragma unroll
        for (int ks = 0; ks < KC; ks += 16) {
            uint32_t ahi[4][4], alo[4][4], bhi[4][2], blo[4][2];
            #pragma unroll
            for (int i = 0; i < 4; i++) {
                int row = wm + i * 16 + g;
                int o0 = row * SSTR + ks + c2;
                int o1 = (row + 8) * SSTR + ks + c2;
                ahi[i][0] = *(const uint32_t*)&Ah[o0];
                ahi[i][1] = *(const uint32_t*)&Ah[o1];
                ahi[i][2] = *(const uint32_t*)&Ah[o0 + 8];
                ahi[i][3] = *(const uint32_t*)&Ah[o1 + 8];
                alo[i][0] = *(const uint32_t*)&Al[o0];
                alo[i][1] = *(const uint32_t*)&Al[o1];
                alo[i][2] = *(const uint32_t*)&Al[o0 + 8];
                alo[i][3] = *(const uint32_t*)&Al[o1 + 8];
            }
            #pragma unroll
            for (int j = 0; j < 4; j++) {
                int col = wn + j * 8 + g;
                int o = col * SSTR + ks + c2;
                bhi[j][0] = *(const uint32_t*)&Bh[o];
                bhi[j][1] = *(const uint32_t*)&Bh[o + 8];
                blo[j][0] = *(const uint32_t*)&Bl[o];
                blo[j][1] = *(const uint32_t*)&Bl[o + 8];
            }
            #pragma unroll
            for (int i = 0; i < 4; i++)
                #pragma unroll
                for (int j = 0; j < 4; j++) {
                    mma_bf16(acc[i][j], ahi[i], bhi[j]);
                    mma_bf16(acc[i][j], ahi[i], blo[j]);
                    mma_bf16(acc[i][j], alo[i], bhi[j]);
                }
        }
    }

    float* C = g_partials + (size_t)blockIdx.y * 128 * ND1;
    #pragma unroll
    for (int i = 0; i < 4; i++) {
        #pragma unroll
        for (int half = 0; half < 2; half++) {
            int m = wm + i * 16 + g + half * 8;
            #pragma unroll
            for (int j = 0; j < 4; j++) {
                int n = n0 + wn + j * 8 + c2;
                *(float2*)(C + (size_t)m * ND1 + n) =
                    make_float2(acc[i][j][half * 2], acc[i][j][half * 2 + 1]);
            }
        }
    }
}

// ---------------------------------------------------------------------------
// Part-stem GEMM on mma.sync bf16x3 (2 CTAs/SM — the single change vs R11)
// ---------------------------------------------------------------------------
__global__ void __launch_bounds__(256, 2) k_part_gemm_mma(const float* __restrict__ Bias) {
    extern __shared__ __nv_bfloat16 smb[];
    __nv_bfloat16* Ah = smb;
    __nv_bfloat16* Al = smb + TILE_E;
    __nv_bfloat16* Bh = smb + 2 * TILE_E;
    __nv_bfloat16* Bl = smb + 3 * TILE_E;

    const int tid = threadIdx.x;
    const int wid = tid >> 5, lane = tid & 31;
    const int n0 = blockIdx.x * 128, m0 = blockIdx.y * 128;
    const int wm = (wid >> 2) * 64, wn = (wid & 3) * 32;
    const int g = lane >> 2, c2 = (lane & 3) * 2;

    float acc[4][4][4];
    #pragma unroll
    for (int i = 0; i < 4; i++)
        #pragma unroll
        for (int j = 0; j < 4; j++)
            #pragma unroll
            for (int r = 0; r < 4; r++) acc[i][j][r] = 0.f;

    for (int kc = 0; kc < KP; kc += KC) {
        __syncthreads();
        for (int idx = tid; idx < 1024; idx += 256) {
            int row = idx >> 3, c8 = (idx & 7) * 8;
            int so = row * SSTR + c8;
            size_t gA = (size_t)(m0 + row) * KP + kc + c8;
            size_t gB = (size_t)(n0 + row) * KP + kc + c8;
            *(uint4*)&Ah[so] = *(const uint4*)&g_Whi[gA];
            *(uint4*)&Al[so] = *(const uint4*)&g_Wlo[gA];
            *(uint4*)&Bh[so] = *(const uint4*)&g_Phi[gB];
            *(uint4*)&Bl[so] = *(const uint4*)&g_Plo[gB];
        }
        __syncthreads();

        #pragma unroll
        for (int ks = 0; ks < KC; ks += 16) {
            uint32_t ahi[4][4], alo[4][4], bhi[4][2], blo[4][2];
            #pragma unroll
            for (int i = 0; i < 4; i++) {
                int row = wm + i * 16 + g;
                int o0 = row * SSTR + ks + c2;
                int o1 = (row + 8) * SSTR + ks + c2;
                ahi[i][0] = *(const uint32_t*)&Ah[o0];
                ahi[i][1] = *(const uint32_t*)&Ah[o1];
                ahi[i][2] = *(const uint32_t*)&Ah[o0 + 8];
                ahi[i][3] = *(const uint32_t*)&Ah[o1 + 8];
                alo[i][0] = *(const uint32_t*)&Al[o0];
                alo[i][1] = *(const uint32_t*)&Al[o1];
                alo[i][2] = *(const uint32_t*)&Al[o0 + 8];
                alo[i][3] = *(const uint32_t*)&Al[o1 + 8];
            }
            #pragma unroll
            for (int j = 0; j < 4; j++) {
                int col = wn + j * 8 + g;
                int o = col * SSTR + ks + c2;
                bhi[j][0] = *(const uint32_t*)&Bh[o];
                bhi[j][1] = *(const uint32_t*)&Bh[o + 8];
                blo[j][0] = *(const uint32_t*)&Bl[o];
                blo[j][1] = *(const uint32_t*)&Bl[o + 8];
            }
            #pragma unroll
            for (int i = 0; i < 4; i++)
                #pragma unroll
                for (int j = 0; j < 4; j++) {
                    mma_bf16(acc[i][j], ahi[i], bhi[j]);
                    mma_bf16(acc[i][j], ahi[i], blo[j]);
                    mma_bf16(acc[i][j], alo[i], bhi[j]);
                }
        }
    }

    #pragma unroll
    for (int i = 0; i < 4; i++) {
        #pragma unroll
        for (int half = 0; half < 2; half++) {
            int m = m0 + wm + i * 16 + g + half * 8;
            float bias = Bias[m];
            int pb = -1; float sum = 0.f;
            #pragma unroll
            for (int j = 0; j < 4; j++) {
                #pragma unroll
                for (int e = 0; e < 2; e++) {
                    int n = n0 + wn + j * 8 + c2 + e;
                    float v = fmaxf(acc[i][j][half * 2 + e] + bias, 0.f);
                    int p = n / NPOS;
                    if (p != pb) {
                        if (pb >= 0) atomicAdd(&g_pfsum[pb * CSTEM + m], sum);
                        sum = 0.f; pb = p;
                    }
                    sum += v;
                }
            }
            atomicAdd(&g_pfsum[pb * CSTEM + m], sum);
        }
    }
}

// ---------------------------------------------------------------------------
// Epilogues / small stages
// ---------------------------------------------------------------------------
__global__ void k_raw_logits(const float* __restrict__ fcw, const float* __restrict__ fcb,
                             float* __restrict__ out) {
    int w = blockIdx.x * 8 + (threadIdx.x >> 5);
    int lane = threadIdx.x & 31;
    if (w >= BATCH * CAT) return;
    int b = w / CAT, j = w % CAT;
    const float* gv = g_gsum + b * CSTEM;
    const float* wv = fcw + (size_t)j * CSTEM;
    float s = 0.f;
    for (int k = lane; k < CSTEM; k += 32) s += gv[k] * wv[k];
    s = warp_red(s);
    if (!lane) out[w] = s / 196.0f + fcb[j];
}

__global__ void k_reduce_d1(const float* __restrict__ d1b) {
    int idx = blockIdx.x * 256 + threadIdx.x;
    if (idx >= BATCH * 128 * NPOS) return;
    int b = idx / (128 * NPOS), r = idx % (128 * NPOS);
    int c = r / NPOS, p = r % NPOS;
    int n = b * NPOS + p;
    float s = 0.f;
    #pragma unroll
    for (int z = 0; z < NSPLIT; z++) s += g_partials[(size_t)(z * 128 + c) * ND1 + n];
    g_d1[idx] = fmaxf(s + d1b[c], 0.f);
}

__global__ void k_down2(const float* __restrict__ w2, const float* __restrict__ b2) {
    int w = blockIdx.x * 8 + (threadIdx.x >> 5);
    int lane = threadIdx.x & 31;
    if (w >= BATCH * 128 * 49) return;
    int b = w / (128 * 49), r = w % (128 * 49);
    int oc = r / 49, pos = r % 49, oy = pos / 7, ox = pos % 7;
    float s = 0.f;
    for (int ic = lane; ic < 128; ic += 32) {
        const float* dp = g_d1 + (size_t)(b * 128 + ic) * NPOS;
        const float* wp = w2 + (size_t)(oc * 128 + ic) * 9;
        #pragma unroll
        for (int ky = 0; ky < 3; ky++) {
            int iy = oy * 2 + ky - 1;
            if ((unsigned)iy >= 14u) continue;
            #pragma unroll
            for (int kx = 0; kx < 3; kx++) {
                int ix = ox * 2 + kx - 1;
                if ((unsigned)ix < 14u) s += wp[ky * 3 + kx] * dp[iy * 14 + ix];
            }
        }
    }
    s = warp_red(s);
    if (!lane) g_d2[w] = fmaxf(s + b2[oc], 0.f);
}

__global__ void k_down3(const float* __restrict__ w3, const float* __restrict__ b3) {
    int w = blockIdx.x * 8 + (threadIdx.x >> 5);
    int lane = threadIdx.x & 31;
    if (w >= BATCH * 128 * 16) return;
    int b = w / (128 * 16), r = w % (128 * 16);
    int oc = r / 16, pos = r % 16, oy = pos / 4, ox = pos % 4;
    float s = 0.f;
    for (int ic = lane; ic < 128; ic += 32) {
        const float* dp = g_d2 + (size_t)(b * 128 + ic) * 49;
        const float* wp = w3 + (size_t)(oc * 128 + ic) * 9;
        #pragma unroll
        for (int ky = 0; ky < 3; ky++) {
            int iy = oy * 2 + ky - 1;
            if ((unsigned)iy >= 7u) continue;
            #pragma unroll
            for (int kx = 0; kx < 3; kx++) {
                int ix = ox * 2 + kx - 1;
                if ((unsigned)ix < 7u) s += wp[ky * 3 + kx] * dp[iy * 7 + ix];
            }
        }
    }
    s = warp_red(s);
    if (!lane) g_d3[w] = fmaxf(s + b3[oc], 0.f);
}

__global__ void k_tidy(const float* __restrict__ w1, const float* __restrict__ b1,
                       const float* __restrict__ w2, const float* __restrict__ b2,
                       const float* __restrict__ w3, const float* __restrict__ b3) {
    int w = blockIdx.x * 8 + (threadIdx.x >> 5);
    int lane = threadIdx.x & 31;
    if (w >= BATCH * NANCH) return;
    int b = w / NANCH, o = w % NANCH;
    const float* src; const float* wt; float bias; int S;
    if (o < 1176)      { int oc = o / 196, pos = o % 196; src = g_d1 + (size_t)b * 128 * 196 + pos; S = 196; wt = w1 + oc * 128; bias = b1[oc]; }
    else if (o < 1470) { int r = o - 1176, oc = r / 49, pos = r % 49; src = g_d2 + (size_t)b * 128 * 49 + pos; S = 49; wt = w2 + oc * 128; bias = b2[oc]; }
    else               { int r = o - 1470, oc = r / 16, pos = r % 16; src = g_d3 + (size_t)b * 128 * 16 + pos; S = 16; wt = w3 + oc * 128; bias = b3[oc]; }
    float s = 0.f;
    for (int ic = lane; ic < 128; ic += 32) s += wt[ic] * src[ic * S];
    s = warp_red(s);
    if (!lane) g_scores[b * NANCH + o] = s + bias;
}

// ---------------------------------------------------------------------------
// NMS (one block per image, matches jnp.argmax first-max tie-break)
// ---------------------------------------------------------------------------
__global__ void k_nms() {
    __shared__ float sm[NANCH];
    __shared__ float rv[256];
    __shared__ int   ri[256];
    int b = blockIdx.x, tid = threadIdx.x;
    for (int i = tid; i < NANCH; i += 256) sm[i] = g_scores[b * NANCH + i];
    __syncthreads();
    for (int t = 0; t < 4; t++) {
        float bv = neg_inf(); int bi = 0x3fffffff;
        for (int i = tid; i < NANCH; i += 256) {
            float v = sm[i];
            if (v > bv || (v == bv && i < bi)) { bv = v; bi = i; }
        }
        rv[tid] = bv; ri[tid] = bi;
        __syncthreads();
        for (int s = 128; s > 0; s >>= 1) {
            if (tid < s) {
                float v2 = rv[tid + s]; int i2 = ri[tid + s];
                if (v2 > rv[tid] || (v2 == rv[tid] && i2 < ri[tid])) { rv[tid] = v2; ri[tid] = i2; }
            }
            __syncthreads();
        }
        int pick = ri[0];
        if (tid == 0) {
            g_pick[b * 4 + t] = pick;
            g_prob[b * 4 + t] = g_scores[b * NANCH + pick];
            int y0 = g_boxi[pick * 4 + 0], x0 = g_boxi[pick * 4 + 1];
            int y1 = max(g_boxi[pick * 4 + 2], y0 + 1);
            int x1 = max(g_boxi[pick * 4 + 3], x0 + 1);
            int pi = b * 4 + t;
            g_cropi[pi * 4 + 0] = y0; g_cropi[pi * 4 + 1] = x0;
            g_cropi[pi * 4 + 2] = y1 - 1; g_cropi[pi * 4 + 3] = x1 - 1;
            g_cropf[pi * 4 + 0] = (float)y0;
            g_cropf[pi * 4 + 1] = __fdiv_rn((float)(y1 - 1 - y0), 447.0f);
            g_cropf[pi * 4 + 2] = (float)x0;
            g_cropf[pi * 4 + 3] = __fdiv_rn((float)(x1 - 1 - x0), 447.0f);
        }
        __syncthreads();
        float py0 = g_boxf[pick * 4], px0 = g_boxf[pick * 4 + 1];
        float py1 = g_boxf[pick * 4 + 2], px1 = g_boxf[pick * 4 + 3];
        float pa = (py1 - py0) * (px1 - px0);
        for (int i = tid; i < NANCH; i += 256) {
            float qy0 = g_boxf[i * 4], qx0 = g_boxf[i * 4 + 1];
            float qy1 = g_boxf[i * 4 + 2], qx1 = g_boxf[i * 4 + 3];
            float t0 = fmaxf(qy0, py0), t1 = fmaxf(qx0, px0);
            float bb0 = fminf(qy1, py1), bb1 = fminf(qx1, px1);
            float w0 = bb0 - t0, w1 = bb1 - t1;
            float inter = (w0 < 0.f || w1 < 0.f) ? 0.f : w0 * w1;
            float qa = (qy1 - qy0) * (qx1 - qx0);
            float iou = inter / (qa + pa - inter);
            if (!(iou < 0.25f)) sm[i] = neg_inf();
        }
        __syncthreads();
    }
}

// ---------------------------------------------------------------------------
// Fused crop-resize + im2col for part stem -> bf16 hi/lo [n][KP]
// ---------------------------------------------------------------------------
__global__ void k_part_im2col(const float* __restrict__ x) {
    int idx = blockIdx.x * 256 + threadIdx.x;
    if (idx >= NPART * KP) return;
    int col = idx / KP, r = idx % KP;
    float v = 0.f;
    if (r < KSTEM) {
        int p = col / NPOS, pos = col % NPOS, oy = pos / 14, ox = pos % 14;
        int c = r / 49, rr = r % 49, dy = rr / 7, dx = rr % 7;
        int iy = oy * 32 + dy - 3, ix = ox * 32 + dx - 3;
        if (iy >= 0 && ix >= 0) {
            int b = p >> 2;
            float y0f = g_cropf[p * 4 + 0], sy = g_cropf[p * 4 + 1];
            float x0f = g_cropf[p * 4 + 2], sx = g_cropf[p * 4 + 3];
            int y1m1 = g_cropi[p * 4 + 2], x1m1 = g_cropi[p * 4 + 3];
            float fy = __fadd_rn(y0f, __fmul_rn((float)iy, sy));
            int yl = (int)floorf(fy);
            float wy = __fsub_rn(fy, (float)yl);
            int yh = min(yl + 1, y1m1);
            float fx = __fadd_rn(x0f, __fmul_rn((float)ix, sx));
            int xl = (int)floorf(fx);
            float wx = __fsub_rn(fx, (float)xl);
            int xh = min(xl + 1, x1m1);
            const float* xb = x + (size_t)(b * 3 + c) * IMH * IMW;
            int ry0 = yl - 224, ry1 = yh - 224, rx0 = xl - 224, rx1 = xh - 224;
            float vll = ((unsigned)ry0 < 448u && (unsigned)rx0 < 448u) ? xb[ry0 * IMW + rx0] : 0.f;
            float vlh = ((unsigned)ry0 < 448u && (unsigned)rx1 < 448u) ? xb[ry0 * IMW + rx1] : 0.f;
            float vhl = ((unsigned)ry1 < 448u && (unsigned)rx0 < 448u) ? xb[ry1 * IMW + rx0] : 0.f;
            float vhh = ((unsigned)ry1 < 448u && (unsigned)rx1 < 448u) ? xb[ry1 * IMW + rx1] : 0.f;
            float omy = __fsub_rn(1.f, wy), omx = __fsub_rn(1.f, wx);
            float top = __fadd_rn(__fmul_rn(omx, vll), __fmul_rn(wx, vlh));
            float bot = __fadd_rn(__fmul_rn(omx, vhl), __fmul_rn(wx, vhh));
            v = __fadd_rn(__fmul_rn(omy, top), __fmul_rn(wy, bot));
        }
    }
    __nv_bfloat16 h = __float2bfloat16(v);
    g_Phi[idx] = h;
    g_Plo[idx] = __float2bfloat16(v - __bfloat162float(h));
}

__global__ void k_fc_concat(const float* __restrict__ cw, const float* __restrict__ cb,
                            float* __restrict__ out) {
    int w = blockIdx.x * 8 + (threadIdx.x >> 5);
    int lane = threadIdx.x & 31;
    if (w >= BATCH * CAT) return;
    int b = w / CAT, j = w % CAT;
    const float* wv = cw + (size_t)j * 10240;
    const float* pfs = g_pfsum + (size_t)b * 4 * CSTEM;
    float s = 0.f;
    for (int k = lane; k < 8192; k += 32) s += pfs[k] * wv[k];
    const float* gv = g_gsum + b * CSTEM;
    for (int k = lane; k < 2048; k += 32) s += gv[k] * wv[8192 + k];
    s = warp_red(s);
    if (!lane) out[1600 + w] = s / 196.0f + cb[j];
}

// part logits + pick/prob tail (fused)
__global__ void k_fc_part(const float* __restrict__ pw, const float* __restrict__ pb,
                          float* __restrict__ out) {
    int w = blockIdx.x * 8 + (threadIdx.x >> 5);
    int lane = threadIdx.x & 31;
    if (blockIdx.x == 0 && threadIdx.x < 32) {
        out[9600 + threadIdx.x] = (float)g_pick[threadIdx.x];
        out[9632 + threadIdx.x] = g_prob[threadIdx.x];
    }
    if (w >= 32 * CAT) return;
    int p = w / CAT, j = w % CAT;
    const float* av = g_pfsum + (size_t)p * CSTEM;
    const float* wv = pw + (size_t)j * CSTEM;
    float s = 0.f;
    for (int k = lane; k < CSTEM; k += 32) s += av[k] * wv[k];
    s = warp_red(s / 196.0f);
    if (!lane) out[3200 + w] = s + pb[j];
}

// ---------------------------------------------------------------------------
// Launch
// ---------------------------------------------------------------------------
extern "C" void kernel_launch(void* const* d_in, const int* in_sizes, int n_in,
                              void* d_out, int out_size) {
    (void)in_sizes; (void)n_in; (void)out_size;
    const float* x      = (const float*)d_in[0];
    const float* stem_w = (const float*)d_in[1];
    const float* stem_b = (const float*)d_in[2];
    const float* fc_w   = (const float*)d_in[3];
    const float* fc_b   = (const float*)d_in[4];
    const float* d1w    = (const float*)d_in[5];
    const float* d1b    = (const float*)d_in[6];
    const float* d2w    = (const float*)d_in[7];
    const float* d2b    = (const float*)d_in[8];
    const float* d3w    = (const float*)d_in[9];
    const float* d3b    = (const float*)d_in[10];
    const float* t1w    = (const float*)d_in[11];
    const float* t1b    = (const float*)d_in[12];
    const float* t2w    = (const float*)d_in[13];
    const float* t2b    = (const float*)d_in[14];
    const float* t3w    = (const float*)d_in[15];
    const float* t3b    = (const float*)d_in[16];
    const float* cw     = (const float*)d_in[17];
    const float* cb     = (const float*)d_in[18];
    const float* pw     = (const float*)d_in[19];
    const float* pb     = (const float*)d_in[20];
    float* out = (float*)d_out;

    cudaFuncSetAttribute(k_stem_gemm_mma, cudaFuncAttributeMaxDynamicSharedMemorySize,
                         SM_MMA_TOTAL);
    cudaFuncSetAttribute(k_d1_gemm_mma, cudaFuncAttributeMaxDynamicSharedMemorySize,
                         SM_MMA_TOTAL);
    cudaFuncSetAttribute(k_part_gemm_mma, cudaFuncAttributeMaxDynamicSharedMemorySize,
                         SM_MMA_TOTAL);

    // prep: anchors + weight hi/lo splits + accumulator zeroing
    k_prep<<<(128 * KD1 + 255) / 256, 256>>>(stem_w, d1w);

    // --- backbone on x: tensor-core stem GEMM (fused relu+pack+pool) ---
    k_im2col_x<<<(NXT * KP + 255) / 256, 256>>>(x);
    k_stem_gemm_mma<<<dim3(NXT / 128, CSTEM / 128), 256, SM_MMA_TOTAL>>>(stem_b);
    k_raw_logits<<<(BATCH * CAT) / 8, 256>>>(fc_w, fc_b, out);

    // --- proposal net: tensor-core d1 GEMM (implicit im2col gather) ---
    k_d1_gemm_mma<<<dim3(ND1 / 128, NSPLIT), 256, SM_MMA_TOTAL>>>();
    k_reduce_d1<<<(BATCH * 128 * NPOS + 255) / 256, 256>>>(d1b);
    k_down2<<<(BATCH * 128 * 49 + 7) / 8, 256>>>(d2w, d2b);
    k_down3<<<(BATCH * 128 * 16 + 7) / 8, 256>>>(d3w, d3b);
    k_tidy<<<(BATCH * NANCH + 7) / 8, 256>>>(t1w, t1b, t2w, t2b, t3w, t3b);

    // --- NMS ---
    k_nms<<<8, 256>>>();

    // --- part branch: crop-resize im2col (bf16 hi/lo) + mma.sync GEMM ---
    k_part_im2col<<<(NPART * KP + 255) / 256, 256>>>(x);
    k_part_gemm_mma<<<dim3(NPART / 128, CSTEM / 128), 256, SM_MMA_TOTAL>>>(stem_b);

    // --- heads ---
    k_fc_concat<<<(BATCH * CAT) / 8, 256>>>(cw, cb, out);
    k_fc_part<<<(32 * CAT) / 8, 256>>>(pw, pb, out);
}

// round 15
// speedup vs baseline: 1.0294x; 1.0085x over previous
#include <cuda_runtime.h>
#include <cuda_bf16.h>
#include <math.h>
#include <stdint.h>

// ---------------------------------------------------------------------------
// Problem dims
// ---------------------------------------------------------------------------
#define BATCH   8
#define IMH     448
#define IMW     448
#define CSTEM   2048
#define KSTEM   147        // 3*7*7
#define KP      192        // padded K for tensor-core stem GEMM
#define NPOS    196        // 14*14
#define NX      1568       // 8*196
#define NXT     1664       // padded cols for stem mma (13*128)
#define ND1     1664       // padded cols for d1 partials (13*128)
#define NPART   6272       // 32*196 = 49*128
#define KD1     18432      // 2048*9
#define NANCH   1614
#define NSPLIT  32         // split-K for down1 (kChunk = 576)
#define CAT     200

// ---------------------------------------------------------------------------
// Scratch (device globals; no runtime allocation)
// ---------------------------------------------------------------------------
__device__ uint32_t g_fhl[BATCH*CSTEM*NPOS];     // stem relu, bf16 hi|lo<<16
__device__ float g_gsum[BATCH*CSTEM];            // global pooled sums (atomic)
__device__ float g_partials[NSPLIT*128*ND1];     // split-K partials
__device__ float g_d1[BATCH*128*NPOS];
__device__ float g_d2[BATCH*128*49];
__device__ float g_d3[BATCH*128*16];
__device__ float g_scores[BATCH*NANCH];
__device__ int   g_boxi[NANCH*4];
__device__ float g_boxf[NANCH*4];
__device__ int   g_pick[32];
__device__ float g_prob[32];
__device__ float g_cropf[32*4];                  // y0f, stepy, x0f, stepx
__device__ int   g_cropi[32*4];                  // y0, x0, y1-1, x1-1
__device__ float g_pfsum[32*CSTEM];              // part pooled sums (atomic)
__device__ __nv_bfloat16 g_Whi[CSTEM*KP];        // stem weights bf16 hi [m][k]
__device__ __nv_bfloat16 g_Wlo[CSTEM*KP];        // stem weights bf16 lo
__device__ __nv_bfloat16 g_Xhi[NXT*KP];          // x im2col bf16 hi [n][k]
__device__ __nv_bfloat16 g_Xlo[NXT*KP];          // x im2col bf16 lo
__device__ __nv_bfloat16 g_Phi[NPART*KP];        // part im2col bf16 hi [n][k]
__device__ __nv_bfloat16 g_Plo[NPART*KP];        // part im2col bf16 lo
__device__ __nv_bfloat16 g_d1whi[128*KD1];       // d1w bf16 hi [m][k]
__device__ __nv_bfloat16 g_d1wlo[128*KD1];       // d1w bf16 lo

#define GRID_PREP ((128 * KD1 / 4 + 255) / 256)  // 2304 blocks (covers all phases)

__device__ __forceinline__ float warp_red(float v) {
    #pragma unroll
    for (int o = 16; o; o >>= 1) v += __shfl_down_sync(0xffffffffu, v, o);
    return v;
}
__device__ __forceinline__ float neg_inf() { return __int_as_float(0xff800000); }

__device__ __forceinline__ uint32_t pack_hilo(float v) {
    __nv_bfloat16 h = __float2bfloat16(v);
    __nv_bfloat16 l = __float2bfloat16(v - __bfloat162float(h));
    uint16_t hu = *(uint16_t*)&h, lu = *(uint16_t*)&l;
    return (uint32_t)hu | ((uint32_t)lu << 16);
}

__device__ __forceinline__ uint16_t bf16_bits(float v) {
    __nv_bfloat16 h = __float2bfloat16(v);
    return *(uint16_t*)&h;
}

// bf16 mma.sync (valid on base sm_100 target)
__device__ __forceinline__ void mma_bf16(float* d, const uint32_t* a, const uint32_t* b) {
    asm volatile(
        "mma.sync.aligned.m16n8k16.row.col.f32.bf16.bf16.f32 "
        "{%0,%1,%2,%3}, {%4,%5,%6,%7}, {%8,%9}, {%0,%1,%2,%3};"
        : "+f"(d[0]), "+f"(d[1]), "+f"(d[2]), "+f"(d[3])
        : "r"(a[0]), "r"(a[1]), "r"(a[2]), "r"(a[3]), "r"(b[0]), "r"(b[1]));
}

// ---------------------------------------------------------------------------
// Prep: anchors + stem/d1 weight bf16 hi/lo (vectorized) + accumulator zeroing
// ---------------------------------------------------------------------------
__global__ void k_prep(const float* __restrict__ sw, const float* __restrict__ d1w) {
    int idx = blockIdx.x * 256 + threadIdx.x;

    if (idx < NANCH) {
        int a = idx;
        int setting, blk, cell, stride, size, ow;
        if (a < 1176)      { setting = 0; blk = a / 196; cell = a % 196; stride = 32;  size = 48;  ow = 14; }
        else if (a < 1470) { setting = 1; int r = a - 1176; blk = r / 49; cell = r % 49; stride = 64;  size = 96;  ow = 7; }
        else               { setting = 2; int r = a - 1470; blk = r / 16; cell = r % 16; stride = 128; size = 192; ow = 4; }
        int si = blk / 3, ai = blk % 3;
        double s;
        if (setting == 2) s = (si == 0) ? 1.0 : (si == 1) ? pow(2.0, 1.0/3.0) : pow(2.0, 2.0/3.0);
        else              s = (si == 0) ? pow(2.0, 1.0/3.0) : pow(2.0, 2.0/3.0);
        double ar = (ai == 0) ? 0.667 : (ai == 1) ? 1.0 : 1.5;
        float cyf = (float)(cell / ow) * (float)stride + (float)stride * 0.5f;
        float cxf = (float)(cell % ow) * (float)stride + (float)stride * 0.5f;
        double hh = (double)size * s / sqrt(ar);
        double ww = (double)size * s * sqrt(ar);
        double e0 = ((double)cyf - hh / 2.0) + 224.0;
        double e1 = ((double)cxf - ww / 2.0) + 224.0;
        double e2 = ((double)cyf + hh / 2.0) + 224.0;
        double e3 = ((double)cxf + ww / 2.0) + 224.0;
        int b0 = (int)e0, b1 = (int)e1, b2 = (int)e2, b3 = (int)e3;
        g_boxi[a*4+0] = b0; g_boxi[a*4+1] = b1; g_boxi[a*4+2] = b2; g_boxi[a*4+3] = b3;
        g_boxf[a*4+0] = (float)b0; g_boxf[a*4+1] = (float)b1;
        g_boxf[a*4+2] = (float)b2; g_boxf[a*4+3] = (float)b3;
    }

    if (idx < CSTEM * KP) {
        int m = idx / KP, k = idx % KP;
        float v = (k < KSTEM) ? sw[m * KSTEM + k] : 0.f;
        __nv_bfloat16 h = __float2bfloat16(v);
        g_Whi[idx] = h;
        g_Wlo[idx] = __float2bfloat16(v - __bfloat162float(h));
    }

    // d1w hi/lo split, 4 elements per thread (vectorized)
    if (idx < 128 * KD1 / 4) {
        float4 v = *(const float4*)&d1w[(size_t)idx * 4];
        uint16_t h0 = bf16_bits(v.x), h1 = bf16_bits(v.y);
        uint16_t h2 = bf16_bits(v.z), h3 = bf16_bits(v.w);
        float r0 = v.x - __bfloat162float(*(__nv_bfloat16*)&h0);
        float r1 = v.y - __bfloat162float(*(__nv_bfloat16*)&h1);
        float r2 = v.z - __bfloat162float(*(__nv_bfloat16*)&h2);
        float r3 = v.w - __bfloat162float(*(__nv_bfloat16*)&h3);
        uint16_t l0 = bf16_bits(r0), l1 = bf16_bits(r1);
        uint16_t l2 = bf16_bits(r2), l3 = bf16_bits(r3);
        uint2 hp = make_uint2((uint32_t)h0 | ((uint32_t)h1 << 16),
                              (uint32_t)h2 | ((uint32_t)h3 << 16));
        uint2 lp = make_uint2((uint32_t)l0 | ((uint32_t)l1 << 16),
                              (uint32_t)l2 | ((uint32_t)l3 << 16));
        *(uint2*)&g_d1whi[(size_t)idx * 4] = hp;
        *(uint2*)&g_d1wlo[(size_t)idx * 4] = lp;
    }

    if (idx < 32 * CSTEM) g_pfsum[idx] = 0.f;
    if (idx < BATCH * CSTEM) g_gsum[idx] = 0.f;
}

// im2col of x -> bf16 hi/lo, [n][KP] layout
__global__ void k_im2col_x(const float* __restrict__ x) {
    int idx = blockIdx.x * 256 + threadIdx.x;
    if (idx >= NXT * KP) return;
    int n = idx / KP, k = idx % KP;
    float v = 0.f;
    if (n < NX && k < KSTEM) {
        int b = n / NPOS, pos = n % NPOS, oy = pos / 14, ox = pos % 14;
        int c = k / 49, rr = k % 49, dy = rr / 7, dx = rr % 7;
        int iy = oy * 32 + dy - 3, ix = ox * 32 + dx - 3;
        if (iy >= 0 && ix >= 0)
            v = x[((b * 3 + c) * IMH + iy) * IMW + ix];
    }
    __nv_bfloat16 h = __float2bfloat16(v);
    g_Xhi[idx] = h;
    g_Xlo[idx] = __float2bfloat16(v - __bfloat162float(h));
}

// ---------------------------------------------------------------------------
// Shared mma tile geometry
// ---------------------------------------------------------------------------
#define KC      64
#define SSTR    72
#define TILE_E  (128 * SSTR)
#define SM_MMA_TOTAL (4 * TILE_E * 2)        // 73728 bytes

// ---------------------------------------------------------------------------
// Stem GEMM on mma.sync bf16x3: W[2048,KP] x X^T[KP,NX]
// Epilogue: bias+relu -> g_fhl (packed) + bucketed atomic global pooling.
// ---------------------------------------------------------------------------
__global__ void __launch_bounds__(256, 2) k_stem_gemm_mma(const float* __restrict__ Bias) {
    extern __shared__ __nv_bfloat16 smb[];
    __nv_bfloat16* Ah = smb;
    __nv_bfloat16* Al = smb + TILE_E;
    __nv_bfloat16* Bh = smb + 2 * TILE_E;
    __nv_bfloat16* Bl = smb + 3 * TILE_E;

    const int tid = threadIdx.x;
    const int wid = tid >> 5, lane = tid & 31;
    const int n0 = blockIdx.x * 128, m0 = blockIdx.y * 128;
    const int wm = (wid >> 2) * 64, wn = (wid & 3) * 32;
    const int g = lane >> 2, c2 = (lane & 3) * 2;

    float acc[4][4][4];
    #pragma unroll
    for (int i = 0; i < 4; i++)
        #pragma unroll
        for (int j = 0; j < 4; j++)
            #pragma unroll
            for (int r = 0; r < 4; r++) acc[i][j][r] = 0.f;

    for (int kc = 0; kc < KP; kc += KC) {
        __syncthreads();
        for (int idx = tid; idx < 1024; idx += 256) {
            int row = idx >> 3, c8 = (idx & 7) * 8;
            int so = row * SSTR + c8;
            size_t gA = (size_t)(m0 + row) * KP + kc + c8;
            size_t gB = (size_t)(n0 + row) * KP + kc + c8;
            *(uint4*)&Ah[so] = *(const uint4*)&g_Whi[gA];
            *(uint4*)&Al[so] = *(const uint4*)&g_Wlo[gA];
            *(uint4*)&Bh[so] = *(const uint4*)&g_Xhi[gB];
            *(uint4*)&Bl[so] = *(const uint4*)&g_Xlo[gB];
        }
        __syncthreads();

        #pragma unroll
        for (int ks = 0; ks < KC; ks += 16) {
            uint32_t ahi[4][4], alo[4][4], bhi[4][2], blo[4][2];
            #pragma unroll
            for (int i = 0; i < 4; i++) {
                int row = wm + i * 16 + g;
                int o0 = row * SSTR + ks + c2;
                int o1 = (row + 8) * SSTR + ks + c2;
                ahi[i][0] = *(const uint32_t*)&Ah[o0];
                ahi[i][1] = *(const uint32_t*)&Ah[o1];
                ahi[i][2] = *(const uint32_t*)&Ah[o0 + 8];
                ahi[i][3] = *(const uint32_t*)&Ah[o1 + 8];
                alo[i][0] = *(const uint32_t*)&Al[o0];
                alo[i][1] = *(const uint32_t*)&Al[o1];
                alo[i][2] = *(const uint32_t*)&Al[o0 + 8];
                alo[i][3] = *(const uint32_t*)&Al[o1 + 8];
            }
            #pragma unroll
            for (int j = 0; j < 4; j++) {
                int col = wn + j * 8 + g;
                int o = col * SSTR + ks + c2;
                bhi[j][0] = *(const uint32_t*)&Bh[o];
                bhi[j][1] = *(const uint32_t*)&Bh[o + 8];
                blo[j][0] = *(const uint32_t*)&Bl[o];
                blo[j][1] = *(const uint32_t*)&Bl[o + 8];
            }
            #pragma unroll
            for (int i = 0; i < 4; i++)
                #pragma unroll
                for (int j = 0; j < 4; j++) {
                    mma_bf16(acc[i][j], ahi[i], bhi[j]);
                    mma_bf16(acc[i][j], ahi[i], blo[j]);
                    mma_bf16(acc[i][j], alo[i], bhi[j]);
                }
        }
    }

    // epilogue: bias+relu -> packed g_fhl, bucketed atomic pooling into g_gsum
    #pragma unroll
    for (int i = 0; i < 4; i++) {
        #pragma unroll
        for (int half = 0; half < 2; half++) {
            int m = m0 + wm + i * 16 + g + half * 8;
            float bias = Bias[m];
            int pb = -1; float sum = 0.f;
            #pragma unroll
            for (int j = 0; j < 4; j++) {
                #pragma unroll
                for (int e = 0; e < 2; e++) {
                    int n = n0 + wn + j * 8 + c2 + e;
                    if (n < NX) {
                        float v = fmaxf(acc[i][j][half * 2 + e] + bias, 0.f);
                        int b = n / NPOS, pos = n % NPOS;
                        g_fhl[((size_t)(b * CSTEM + m)) * NPOS + pos] = pack_hilo(v);
                        if (b != pb) {
                            if (pb >= 0) atomicAdd(&g_gsum[pb * CSTEM + m], sum);
                            sum = 0.f; pb = b;
                        }
                        sum += v;
                    }
                }
            }
            if (pb >= 0) atomicAdd(&g_gsum[pb * CSTEM + m], sum);
        }
    }
}

// ---------------------------------------------------------------------------
// down1 GEMM on mma.sync bf16x3 (B gathered implicitly from packed g_fhl)
// ---------------------------------------------------------------------------
__global__ void __launch_bounds__(256, 2) k_d1_gemm_mma() {
    extern __shared__ __nv_bfloat16 smb[];
    __nv_bfloat16* Ah = smb;
    __nv_bfloat16* Al = smb + TILE_E;
    __nv_bfloat16* Bh = smb + 2 * TILE_E;
    __nv_bfloat16* Bl = smb + 3 * TILE_E;

    const int tid = threadIdx.x;
    const int wid = tid >> 5, lane = tid & 31;
    const int n0 = blockIdx.x * 128;
    const int kStart = blockIdx.y * (KD1 / NSPLIT);
    const int wm = (wid >> 2) * 64, wn = (wid & 3) * 32;
    const int g = lane >> 2, c2 = (lane & 3) * 2;

    const int bcol = tid & 127;
    const int kh = tid >> 7;         // 0 or 1: which 32-k half
    const int nB = n0 + bcol;
    const bool bval = nB < NX;
    int bb = 0, boy = 0, box = 0;
    if (bval) { bb = nB / NPOS; int pos = nB % NPOS; boy = pos / 14; box = pos % 14; }

    float acc[4][4][4];
    #pragma unroll
    for (int i = 0; i < 4; i++)
        #pragma unroll
        for (int j = 0; j < 4; j++)
            #pragma unroll
            for (int r = 0; r < 4; r++) acc[i][j][r] = 0.f;

    for (int kc = 0; kc < KD1 / NSPLIT; kc += KC) {
        int k0 = kStart + kc;
        __syncthreads();
        // A: pure uint4 copies
        for (int idx = tid; idx < 1024; idx += 256) {
            int row = idx >> 3, c8 = (idx & 7) * 8;
            int so = row * SSTR + c8;
            size_t gA = (size_t)row * KD1 + k0 + c8;
            *(uint4*)&Ah[so] = *(const uint4*)&g_d1whi[gA];
            *(uint4*)&Al[so] = *(const uint4*)&g_d1wlo[gA];
        }
        // B: implicit im2col gather, 2 k per u32 store
        #pragma unroll 4
        for (int kk = kh * 32; kk < kh * 32 + 32; kk += 2) {
            int k = k0 + kk;
            int c0 = k / 9, t90 = k - 9 * c0;
            int iy0 = boy + t90 / 3 - 1, ix0 = box + (t90 - 3 * (t90 / 3)) - 1;
            uint32_t v0 = 0;
            if (bval && (unsigned)iy0 < 14u && (unsigned)ix0 < 14u)
                v0 = g_fhl[((size_t)(bb * CSTEM + c0)) * NPOS + iy0 * 14 + ix0];
            int k1 = k + 1;
            int c1 = k1 / 9, t91 = k1 - 9 * c1;
            int iy1 = boy + t91 / 3 - 1, ix1 = box + (t91 - 3 * (t91 / 3)) - 1;
            uint32_t v1 = 0;
            if (bval && (unsigned)iy1 < 14u && (unsigned)ix1 < 14u)
                v1 = g_fhl[((size_t)(bb * CSTEM + c1)) * NPOS + iy1 * 14 + ix1];
            int so = bcol * SSTR + kk;   // even offset -> u32-aligned
            *(uint32_t*)&Bh[so] = (v0 & 0xFFFFu) | ((v1 & 0xFFFFu) << 16);
            *(uint32_t*)&Bl[so] = (v0 >> 16) | (v1 & 0xFFFF0000u);
        }
        __syncthreads();

        #pragma unroll
        for (int ks = 0; ks < KC; ks += 16) {
            uint32_t ahi[4][4], alo[4][4], bhi[4][2], blo[4][2];
            #pragma unroll
            for (int i = 0; i < 4; i++) {
                int row = wm + i * 16 + g;
                int o0 = row * SSTR + ks + c2;
                int o1 = (row + 8) * SSTR + ks + c2;
                ahi[i][0] = *(const uint32_t*)&Ah[o0];
                ahi[i][1] = *(const uint32_t*)&Ah[o1];
                ahi[i][2] = *(const uint32_t*)&Ah[o0 + 8];
                ahi[i][3] = *(const uint32_t*)&Ah[o1 + 8];
                alo[i][0] = *(const uint32_t*)&Al[o0];
                alo[i][1] = *(const uint32_t*)&Al[o1];
                alo[i][2] = *(const uint32_t*)&Al[o0 + 8];
                alo[i][3] = *(const uint32_t*)&Al[o1 + 8];
            }
            #pragma unroll
            for (int j = 0; j < 4; j++) {
                int col = wn + j * 8 + g;
                int o = col * SSTR + ks + c2;
                bhi[j][0] = *(const uint32_t*)&Bh[o];
                bhi[j][1] = *(const uint32_t*)&Bh[o + 8];
                blo[j][0] = *(const uint32_t*)&Bl[o];
                blo[j][1] = *(const uint32_t*)&Bl[o + 8];
            }
            #pragma unroll
            for (int i = 0; i < 4; i++)
                #pragma unroll
                for (int j = 0; j < 4; j++) {
                    mma_bf16(acc[i][j], ahi[i], bhi[j]);
                    mma_bf16(acc[i][j], ahi[i], blo[j]);
                    mma_bf16(acc[i][j], alo[i], bhi[j]);
                }
        }
    }

    float* C = g_partials + (size_t)blockIdx.y * 128 * ND1;
    #pragma unroll
    for (int i = 0; i < 4; i++) {
        #pragma unroll
        for (int half = 0; half < 2; half++) {
            int m = wm + i * 16 + g + half * 8;
            #pragma unroll
            for (int j = 0; j < 4; j++) {
                int n = n0 + wn + j * 8 + c2;
                *(float2*)(C + (size_t)m * ND1 + n) =
                    make_float2(acc[i][j][half * 2], acc[i][j][half * 2 + 1]);
            }
        }
    }
}

// ---------------------------------------------------------------------------
// Part-stem GEMM on mma.sync bf16x3 (2 CTAs/SM)
// ---------------------------------------------------------------------------
__global__ void __launch_bounds__(256, 2) k_part_gemm_mma(const float* __restrict__ Bias) {
    extern __shared__ __nv_bfloat16 smb[];
    __nv_bfloat16* Ah = smb;
    __nv_bfloat16* Al = smb + TILE_E;
    __nv_bfloat16* Bh = smb + 2 * TILE_E;
    __nv_bfloat16* Bl = smb + 3 * TILE_E;

    const int tid = threadIdx.x;
    const int wid = tid >> 5, lane = tid & 31;
    const int n0 = blockIdx.x * 128, m0 = blockIdx.y * 128;
    const int wm = (wid >> 2) * 64, wn = (wid & 3) * 32;
    const int g = lane >> 2, c2 = (lane & 3) * 2;

    float acc[4][4][4];
    #pragma unroll
    for (int i = 0; i < 4; i++)
        #pragma unroll
        for (int j = 0; j < 4; j++)
            #pragma unroll
            for (int r = 0; r < 4; r++) acc[i][j][r] = 0.f;

    for (int kc = 0; kc < KP; kc += KC) {
        __syncthreads();
        for (int idx = tid; idx < 1024; idx += 256) {
            int row = idx >> 3, c8 = (idx & 7) * 8;
            int so = row * SSTR + c8;
            size_t gA = (size_t)(m0 + row) * KP + kc + c8;
            size_t gB = (size_t)(n0 + row) * KP + kc + c8;
            *(uint4*)&Ah[so] = *(const uint4*)&g_Whi[gA];
            *(uint4*)&Al[so] = *(const uint4*)&g_Wlo[gA];
            *(uint4*)&Bh[so] = *(const uint4*)&g_Phi[gB];
            *(uint4*)&Bl[so] = *(const uint4*)&g_Plo[gB];
        }
        __syncthreads();

        #pragma unroll
        for (int ks = 0; ks < KC; ks += 16) {
            uint32_t ahi[4][4], alo[4][4], bhi[4][2], blo[4][2];
            #pragma unroll
            for (int i = 0; i < 4; i++) {
                int row = wm + i * 16 + g;
                int o0 = row * SSTR + ks + c2;
                int o1 = (row + 8) * SSTR + ks + c2;
                ahi[i][0] = *(const uint32_t*)&Ah[o0];
                ahi[i][1] = *(const uint32_t*)&Ah[o1];
                ahi[i][2] = *(const uint32_t*)&Ah[o0 + 8];
                ahi[i][3] = *(const uint32_t*)&Ah[o1 + 8];
                alo[i][0] = *(const uint32_t*)&Al[o0];
                alo[i][1] = *(const uint32_t*)&Al[o1];
                alo[i][2] = *(const uint32_t*)&Al[o0 + 8];
                alo[i][3] = *(const uint32_t*)&Al[o1 + 8];
            }
            #pragma unroll
            for (int j = 0; j < 4; j++) {
                int col = wn + j * 8 + g;
                int o = col * SSTR + ks + c2;
                bhi[j][0] = *(const uint32_t*)&Bh[o];
                bhi[j][1] = *(const uint32_t*)&Bh[o + 8];
                blo[j][0] = *(const uint32_t*)&Bl[o];
                blo[j][1] = *(const uint32_t*)&Bl[o + 8];
            }
            #pragma unroll
            for (int i = 0; i < 4; i++)
                #pragma unroll
                for (int j = 0; j < 4; j++) {
                    mma_bf16(acc[i][j], ahi[i], bhi[j]);
                    mma_bf16(acc[i][j], ahi[i], blo[j]);
                    mma_bf16(acc[i][j], alo[i], bhi[j]);
                }
        }
    }

    #pragma unroll
    for (int i = 0; i < 4; i++) {
        #pragma unroll
        for (int half = 0; half < 2; half++) {
            int m = m0 + wm + i * 16 + g + half * 8;
            float bias = Bias[m];
            int pb = -1; float sum = 0.f;
            #pragma unroll
            for (int j = 0; j < 4; j++) {
                #pragma unroll
                for (int e = 0; e < 2; e++) {
                    int n = n0 + wn + j * 8 + c2 + e;
                    float v = fmaxf(acc[i][j][half * 2 + e] + bias, 0.f);
                    int p = n / NPOS;
                    if (p != pb) {
                        if (pb >= 0) atomicAdd(&g_pfsum[pb * CSTEM + m], sum);
                        sum = 0.f; pb = p;
                    }
                    sum += v;
                }
            }
            atomicAdd(&g_pfsum[pb * CSTEM + m], sum);
        }
    }
}

// ---------------------------------------------------------------------------
// Epilogues / small stages
// ---------------------------------------------------------------------------
__global__ void k_raw_logits(const float* __restrict__ fcw, const float* __restrict__ fcb,
                             float* __restrict__ out) {
    int w = blockIdx.x * 8 + (threadIdx.x >> 5);
    int lane = threadIdx.x & 31;
    if (w >= BATCH * CAT) return;
    int b = w / CAT, j = w % CAT;
    const float* gv = g_gsum + b * CSTEM;
    const float* wv = fcw + (size_t)j * CSTEM;
    float s = 0.f;
    for (int k = lane; k < CSTEM; k += 32) s += gv[k] * wv[k];
    s = warp_red(s);
    if (!lane) out[w] = s / 196.0f + fcb[j];
}

// vectorized split-K reduce: 4 consecutive n per thread (float4)
__global__ void k_reduce_d1(const float* __restrict__ d1b) {
    int idx = blockIdx.x * 256 + threadIdx.x;
    if (idx >= BATCH * 128 * NPOS / 4) return;
    int q = idx * 4;
    int b = q / (128 * NPOS), r = q % (128 * NPOS);
    int c = r / NPOS, p = r % NPOS;          // p multiple of 4 (196 % 4 == 0)
    int n = b * NPOS + p;
    float4 s = make_float4(0.f, 0.f, 0.f, 0.f);
    #pragma unroll
    for (int z = 0; z < NSPLIT; z++) {
        float4 v = *(const float4*)&g_partials[(size_t)(z * 128 + c) * ND1 + n];
        s.x += v.x; s.y += v.y; s.z += v.z; s.w += v.w;
    }
    float bias = d1b[c];
    *(float4*)&g_d1[q] = make_float4(fmaxf(s.x + bias, 0.f), fmaxf(s.y + bias, 0.f),
                                     fmaxf(s.z + bias, 0.f), fmaxf(s.w + bias, 0.f));
}

__global__ void k_down2(const float* __restrict__ w2, const float* __restrict__ b2) {
    int w = blockIdx.x * 8 + (threadIdx.x >> 5);
    int lane = threadIdx.x & 31;
    if (w >= BATCH * 128 * 49) return;
    int b = w / (128 * 49), r = w % (128 * 49);
    int oc = r / 49, pos = r % 49, oy = pos / 7, ox = pos % 7;
    float s = 0.f;
    for (int ic = lane; ic < 128; ic += 32) {
        const float* dp = g_d1 + (size_t)(b * 128 + ic) * NPOS;
        const float* wp = w2 + (size_t)(oc * 128 + ic) * 9;
        #pragma unroll
        for (int ky = 0; ky < 3; ky++) {
            int iy = oy * 2 + ky - 1;
            if ((unsigned)iy >= 14u) continue;
            #pragma unroll
            for (int kx = 0; kx < 3; kx++) {
                int ix = ox * 2 + kx - 1;
                if ((unsigned)ix < 14u) s += wp[ky * 3 + kx] * dp[iy * 14 + ix];
            }
        }
    }
    s = warp_red(s);
    if (!lane) g_d2[w] = fmaxf(s + b2[oc], 0.f);
}

__global__ void k_down3(const float* __restrict__ w3, const float* __restrict__ b3) {
    int w = blockIdx.x * 8 + (threadIdx.x >> 5);
    int lane = threadIdx.x & 31;
    if (w >= BATCH * 128 * 16) return;
    int b = w / (128 * 16), r = w % (128 * 16);
    int oc = r / 16, pos = r % 16, oy = pos / 4, ox = pos % 4;
    float s = 0.f;
    for (int ic = lane; ic < 128; ic += 32) {
        const float* dp = g_d2 + (size_t)(b * 128 + ic) * 49;
        const float* wp = w3 + (size_t)(oc * 128 + ic) * 9;
        #pragma unroll
        for (int ky = 0; ky < 3; ky++) {
            int iy = oy * 2 + ky - 1;
            if ((unsigned)iy >= 7u) continue;
            #pragma unroll
            for (int kx = 0; kx < 3; kx++) {
                int ix = ox * 2 + kx - 1;
                if ((unsigned)ix < 7u) s += wp[ky * 3 + kx] * dp[iy * 7 + ix];
            }
        }
    }
    s = warp_red(s);
    if (!lane) g_d3[w] = fmaxf(s + b3[oc], 0.f);
}

__global__ void k_tidy(const float* __restrict__ w1, const float* __restrict__ b1,
                       const float* __restrict__ w2, const float* __restrict__ b2,
                       const float* __restrict__ w3, const float* __restrict__ b3) {
    int w = blockIdx.x * 8 + (threadIdx.x >> 5);
    int lane = threadIdx.x & 31;
    if (w >= BATCH * NANCH) return;
    int b = w / NANCH, o = w % NANCH;
    const float* src; const float* wt; float bias; int S;
    if (o < 1176)      { int oc = o / 196, pos = o % 196; src = g_d1 + (size_t)b * 128 * 196 + pos; S = 196; wt = w1 + oc * 128; bias = b1[oc]; }
    else if (o < 1470) { int r = o - 1176, oc = r / 49, pos = r % 49; src = g_d2 + (size_t)b * 128 * 49 + pos; S = 49; wt = w2 + oc * 128; bias = b2[oc]; }
    else               { int r = o - 1470, oc = r / 16, pos = r % 16; src = g_d3 + (size_t)b * 128 * 16 + pos; S = 16; wt = w3 + oc * 128; bias = b3[oc]; }
    float s = 0.f;
    for (int ic = lane; ic < 128; ic += 32) s += wt[ic] * src[ic * S];
    s = warp_red(s);
    if (!lane) g_scores[b * NANCH + o] = s + bias;
}

// ---------------------------------------------------------------------------
// NMS (one block per image, matches jnp.argmax first-max tie-break)
// ---------------------------------------------------------------------------
__global__ void k_nms() {
    __shared__ float sm[NANCH];
    __shared__ float rv[256];
    __shared__ int   ri[256];
    int b = blockIdx.x, tid = threadIdx.x;
    for (int i = tid; i < NANCH; i += 256) sm[i] = g_scores[b * NANCH + i];
    __syncthreads();
    for (int t = 0; t < 4; t++) {
        float bv = neg_inf(); int bi = 0x3fffffff;
        for (int i = tid; i < NANCH; i += 256) {
            float v = sm[i];
            if (v > bv || (v == bv && i < bi)) { bv = v; bi = i; }
        }
        rv[tid] = bv; ri[tid] = bi;
        __syncthreads();
        for (int s = 128; s > 0; s >>= 1) {
            if (tid < s) {
                float v2 = rv[tid + s]; int i2 = ri[tid + s];
                if (v2 > rv[tid] || (v2 == rv[tid] && i2 < ri[tid])) { rv[tid] = v2; ri[tid] = i2; }
            }
            __syncthreads();
        }
        int pick = ri[0];
        if (tid == 0) {
            g_pick[b * 4 + t] = pick;
            g_prob[b * 4 + t] = g_scores[b * NANCH + pick];
            int y0 = g_boxi[pick * 4 + 0], x0 = g_boxi[pick * 4 + 1];
            int y1 = max(g_boxi[pick * 4 + 2], y0 + 1);
            int x1 = max(g_boxi[pick * 4 + 3], x0 + 1);
            int pi = b * 4 + t;
            g_cropi[pi * 4 + 0] = y0; g_cropi[pi * 4 + 1] = x0;
            g_cropi[pi * 4 + 2] = y1 - 1; g_cropi[pi * 4 + 3] = x1 - 1;
            g_cropf[pi * 4 + 0] = (float)y0;
            g_cropf[pi * 4 + 1] = __fdiv_rn((float)(y1 - 1 - y0), 447.0f);
            g_cropf[pi * 4 + 2] = (float)x0;
            g_cropf[pi * 4 + 3] = __fdiv_rn((float)(x1 - 1 - x0), 447.0f);
        }
        __syncthreads();
        float py0 = g_boxf[pick * 4], px0 = g_boxf[pick * 4 + 1];
        float py1 = g_boxf[pick * 4 + 2], px1 = g_boxf[pick * 4 + 3];
        float pa = (py1 - py0) * (px1 - px0);
        for (int i = tid; i < NANCH; i += 256) {
            float qy0 = g_boxf[i * 4], qx0 = g_boxf[i * 4 + 1];
            float qy1 = g_boxf[i * 4 + 2], qx1 = g_boxf[i * 4 + 3];
            float t0 = fmaxf(qy0, py0), t1 = fmaxf(qx0, px0);
            float bb0 = fminf(qy1, py1), bb1 = fminf(qx1, px1);
            float w0 = bb0 - t0, w1 = bb1 - t1;
            float inter = (w0 < 0.f || w1 < 0.f) ? 0.f : w0 * w1;
            float qa = (qy1 - qy0) * (qx1 - qx0);
            float iou = inter / (qa + pa - inter);
            if (!(iou < 0.25f)) sm[i] = neg_inf();
        }
        __syncthreads();
    }
}

// ---------------------------------------------------------------------------
// Fused crop-resize + im2col for part stem -> bf16 hi/lo [n][KP]
// ---------------------------------------------------------------------------
__global__ void k_part_im2col(const float* __restrict__ x) {
    int idx = blockIdx.x * 256 + threadIdx.x;
    if (idx >= NPART * KP) return;
    int col = idx / KP, r = idx % KP;
    float v = 0.f;
    if (r < KSTEM) {
        int p = col / NPOS, pos = col % NPOS, oy = pos / 14, ox = pos % 14;
        int c = r / 49, rr = r % 49, dy = rr / 7, dx = rr % 7;
        int iy = oy * 32 + dy - 3, ix = ox * 32 + dx - 3;
        if (iy >= 0 && ix >= 0) {
            int b = p >> 2;
            float y0f = g_cropf[p * 4 + 0], sy = g_cropf[p * 4 + 1];
            float x0f = g_cropf[p * 4 + 2], sx = g_cropf[p * 4 + 3];
            int y1m1 = g_cropi[p * 4 + 2], x1m1 = g_cropi[p * 4 + 3];
            float fy = __fadd_rn(y0f, __fmul_rn((float)iy, sy));
            int yl = (int)floorf(fy);
            float wy = __fsub_rn(fy, (float)yl);
            int yh = min(yl + 1, y1m1);
            float fx = __fadd_rn(x0f, __fmul_rn((float)ix, sx));
            int xl = (int)floorf(fx);
            float wx = __fsub_rn(fx, (float)xl);
            int xh = min(xl + 1, x1m1);
            const float* xb = x + (size_t)(b * 3 + c) * IMH * IMW;
            int ry0 = yl - 224, ry1 = yh - 224, rx0 = xl - 224, rx1 = xh - 224;
            float vll = ((unsigned)ry0 < 448u && (unsigned)rx0 < 448u) ? xb[ry0 * IMW + rx0] : 0.f;
            float vlh = ((unsigned)ry0 < 448u && (unsigned)rx1 < 448u) ? xb[ry0 * IMW + rx1] : 0.f;
            float vhl = ((unsigned)ry1 < 448u && (unsigned)rx0 < 448u) ? xb[ry1 * IMW + rx0] : 0.f;
            float vhh = ((unsigned)ry1 < 448u && (unsigned)rx1 < 448u) ? xb[ry1 * IMW + rx1] : 0.f;
            float omy = __fsub_rn(1.f, wy), omx = __fsub_rn(1.f, wx);
            float top = __fadd_rn(__fmul_rn(omx, vll), __fmul_rn(wx, vlh));
            float bot = __fadd_rn(__fmul_rn(omx, vhl), __fmul_rn(wx, vhh));
            v = __fadd_rn(__fmul_rn(omy, top), __fmul_rn(wy, bot));
        }
    }
    __nv_bfloat16 h = __float2bfloat16(v);
    g_Phi[idx] = h;
    g_Plo[idx] = __float2bfloat16(v - __bfloat162float(h));
}

__global__ void k_fc_concat(const float* __restrict__ cw, const float* __restrict__ cb,
                            float* __restrict__ out) {
    int w = blockIdx.x * 8 + (threadIdx.x >> 5);
    int lane = threadIdx.x & 31;
    if (w >= BATCH * CAT) return;
    int b = w / CAT, j = w % CAT;
    const float* wv = cw + (size_t)j * 10240;
    const float* pfs = g_pfsum + (size_t)b * 4 * CSTEM;
    float s = 0.f;
    for (int k = lane; k < 8192; k += 32) s += pfs[k] * wv[k];
    const float* gv = g_gsum + b * CSTEM;
    for (int k = lane; k < 2048; k += 32) s += gv[k] * wv[8192 + k];
    s = warp_red(s);
    if (!lane) out[1600 + w] = s / 196.0f + cb[j];
}

// part logits + pick/prob tail (fused)
__global__ void k_fc_part(const float* __restrict__ pw, const float* __restrict__ pb,
                          float* __restrict__ out) {
    int w = blockIdx.x * 8 + (threadIdx.x >> 5);
    int lane = threadIdx.x & 31;
    if (blockIdx.x == 0 && threadIdx.x < 32) {
        out[9600 + threadIdx.x] = (float)g_pick[threadIdx.x];
        out[9632 + threadIdx.x] = g_prob[threadIdx.x];
    }
    if (w >= 32 * CAT) return;
    int p = w / CAT, j = w % CAT;
    const float* av = g_pfsum + (size_t)p * CSTEM;
    const float* wv = pw + (size_t)j * CSTEM;
    float s = 0.f;
    for (int k = lane; k < CSTEM; k += 32) s += av[k] * wv[k];
    s = warp_red(s / 196.0f);
    if (!lane) out[3200 + w] = s + pb[j];
}

// ---------------------------------------------------------------------------
// Launch
// ---------------------------------------------------------------------------
extern "C" void kernel_launch(void* const* d_in, const int* in_sizes, int n_in,
                              void* d_out, int out_size) {
    (void)in_sizes; (void)n_in; (void)out_size;
    const float* x      = (const float*)d_in[0];
    const float* stem_w = (const float*)d_in[1];
    const float* stem_b = (const float*)d_in[2];
    const float* fc_w   = (const float*)d_in[3];
    const float* fc_b   = (const float*)d_in[4];
    const float* d1w    = (const float*)d_in[5];
    const float* d1b    = (const float*)d_in[6];
    const float* d2w    = (const float*)d_in[7];
    const float* d2b    = (const float*)d_in[8];
    const float* d3w    = (const float*)d_in[9];
    const float* d3b    = (const float*)d_in[10];
    const float* t1w    = (const float*)d_in[11];
    const float* t1b    = (const float*)d_in[12];
    const float* t2w    = (const float*)d_in[13];
    const float* t2b    = (const float*)d_in[14];
    const float* t3w    = (const float*)d_in[15];
    const float* t3b    = (const float*)d_in[16];
    const float* cw     = (const float*)d_in[17];
    const float* cb     = (const float*)d_in[18];
    const float* pw     = (const float*)d_in[19];
    const float* pb     = (const float*)d_in[20];
    float* out = (float*)d_out;

    cudaFuncSetAttribute(k_stem_gemm_mma, cudaFuncAttributeMaxDynamicSharedMemorySize,
                         SM_MMA_TOTAL);
    cudaFuncSetAttribute(k_d1_gemm_mma, cudaFuncAttributeMaxDynamicSharedMemorySize,
                         SM_MMA_TOTAL);
    cudaFuncSetAttribute(k_part_gemm_mma, cudaFuncAttributeMaxDynamicSharedMemorySize,
                         SM_MMA_TOTAL);

    // prep: anchors + weight hi/lo splits (vectorized d1w) + accumulator zeroing
    k_prep<<<GRID_PREP, 256>>>(stem_w, d1w);

    // --- backbone on x: tensor-core stem GEMM (fused relu+pack+pool) ---
    k_im2col_x<<<(NXT * KP + 255) / 256, 256>>>(x);
    k_stem_gemm_mma<<<dim3(NXT / 128, CSTEM / 128), 256, SM_MMA_TOTAL>>>(stem_b);
    k_raw_logits<<<(BATCH * CAT) / 8, 256>>>(fc_w, fc_b, out);

    // --- proposal net: tensor-core d1 GEMM (implicit im2col gather) ---
    k_d1_gemm_mma<<<dim3(ND1 / 128, NSPLIT), 256, SM_MMA_TOTAL>>>();
    k_reduce_d1<<<(BATCH * 128 * NPOS / 4 + 255) / 256, 256>>>(d1b);
    k_down2<<<(BATCH * 128 * 49 + 7) / 8, 256>>>(d2w, d2b);
    k_down3<<<(BATCH * 128 * 16 + 7) / 8, 256>>>(d3w, d3b);
    k_tidy<<<(BATCH * NANCH + 7) / 8, 256>>>(t1w, t1b, t2w, t2b, t3w, t3b);

    // --- NMS ---
    k_nms<<<8, 256>>>();

    // --- part branch: crop-resize im2col (bf16 hi/lo) + mma.sync GEMM ---
    k_part_im2col<<<(NPART * KP + 255) / 256, 256>>>(x);
    k_part_gemm_mma<<<dim3(NPART / 128, CSTEM / 128), 256, SM_MMA_TOTAL>>>(stem_b);

    // --- heads ---
    k_fc_concat<<<(BATCH * CAT) / 8, 256>>>(cw, cb, out);
    k_fc_part<<<(32 * CAT) / 8, 256>>>(pw, pb, out);
}

// round 17
// speedup vs baseline: 1.0790x; 1.0482x over previous
#include <cuda_runtime.h>
#include <cuda_bf16.h>
#include <math.h>
#include <stdint.h>

// ---------------------------------------------------------------------------
// Problem dims
// ---------------------------------------------------------------------------
#define BATCH   8
#define IMH     448
#define IMW     448
#define CSTEM   2048
#define KSTEM   147        // 3*7*7
#define KP      192        // padded K for tensor-core stem GEMM
#define NPOS    196        // 14*14
#define NX      1568       // 8*196
#define NXT     1664       // padded cols for stem mma (13*128)
#define ND1     1664       // padded cols for d1 partials (13*128)
#define NPART   6272       // 32*196 = 49*128
#define KD1     18432      // 2048*9
#define NANCH   1614
#define NSPLIT  32         // split-K for down1 (kChunk = 576)
#define CAT     200

// ---------------------------------------------------------------------------
// Scratch (device globals; no runtime allocation)
// ---------------------------------------------------------------------------
__device__ uint32_t g_fhl[BATCH*CSTEM*NPOS];     // stem relu, bf16 hi|lo<<16
__device__ float g_gsum[BATCH*CSTEM];            // global pooled sums (atomic)
__device__ float g_partials[NSPLIT*128*ND1];     // split-K partials
__device__ float g_d1[BATCH*128*NPOS];
__device__ float g_d2[BATCH*128*49];
__device__ float g_d3[BATCH*128*16];
__device__ float g_scores[BATCH*NANCH];
__device__ int   g_boxi[NANCH*4];
__device__ float g_boxf[NANCH*4];
__device__ int   g_pick[32];
__device__ float g_prob[32];
__device__ float g_cropf[32*4];                  // y0f, stepy, x0f, stepx
__device__ int   g_cropi[32*4];                  // y0, x0, y1-1, x1-1
__device__ float g_pfsum[32*CSTEM];              // part pooled sums (atomic)
__device__ __nv_bfloat16 g_Whi[CSTEM*KP];        // stem weights bf16 hi [m][k]
__device__ __nv_bfloat16 g_Wlo[CSTEM*KP];        // stem weights bf16 lo
__device__ __nv_bfloat16 g_Xhi[NXT*KP];          // x im2col bf16 hi [n][k]
__device__ __nv_bfloat16 g_Xlo[NXT*KP];          // x im2col bf16 lo
__device__ __nv_bfloat16 g_Phi[NPART*KP];        // part im2col bf16 hi [n][k]
__device__ __nv_bfloat16 g_Plo[NPART*KP];        // part im2col bf16 lo
__device__ __nv_bfloat16 g_d1whi[128*KD1];       // d1w bf16 hi [m][k]
__device__ __nv_bfloat16 g_d1wlo[128*KD1];       // d1w bf16 lo

#define GRID_PREP ((128 * KD1 / 4 + 255) / 256)  // 2304 blocks (covers all phases)

__device__ __forceinline__ float warp_red(float v) {
    #pragma unroll
    for (int o = 16; o; o >>= 1) v += __shfl_down_sync(0xffffffffu, v, o);
    return v;
}
__device__ __forceinline__ float neg_inf() { return __int_as_float(0xff800000); }

__device__ __forceinline__ uint32_t pack_hilo(float v) {
    __nv_bfloat16 h = __float2bfloat16(v);
    __nv_bfloat16 l = __float2bfloat16(v - __bfloat162float(h));
    uint16_t hu = *(uint16_t*)&h, lu = *(uint16_t*)&l;
    return (uint32_t)hu | ((uint32_t)lu << 16);
}

__device__ __forceinline__ uint16_t bf16_bits(float v) {
    __nv_bfloat16 h = __float2bfloat16(v);
    return *(uint16_t*)&h;
}

// bf16 mma.sync (valid on base sm_100 target)
__device__ __forceinline__ void mma_bf16(float* d, const uint32_t* a, const uint32_t* b) {
    asm volatile(
        "mma.sync.aligned.m16n8k16.row.col.f32.bf16.bf16.f32 "
        "{%0,%1,%2,%3}, {%4,%5,%6,%7}, {%8,%9}, {%0,%1,%2,%3};"
        : "+f"(d[0]), "+f"(d[1]), "+f"(d[2]), "+f"(d[3])
        : "r"(a[0]), "r"(a[1]), "r"(a[2]), "r"(a[3]), "r"(b[0]), "r"(b[1]));
}

// cp.async 16B: global -> shared without register round-trip (Ampere+)
__device__ __forceinline__ void cp_async16(void* smem_dst, const void* gmem_src) {
    uint32_t s = (uint32_t)__cvta_generic_to_shared(smem_dst);
    asm volatile("cp.async.ca.shared.global [%0], [%1], 16;" :: "r"(s), "l"(gmem_src) : "memory");
}
__device__ __forceinline__ void cp_async_wait_all() {
    asm volatile("cp.async.commit_group;\ncp.async.wait_group 0;" ::: "memory");
}

// ---------------------------------------------------------------------------
// Prep: anchors + stem/d1 weight bf16 hi/lo (vectorized) + accumulator zeroing
// ---------------------------------------------------------------------------
__global__ void k_prep(const float* __restrict__ sw, const float* __restrict__ d1w) {
    int idx = blockIdx.x * 256 + threadIdx.x;

    if (idx < NANCH) {
        int a = idx;
        int setting, blk, cell, stride, size, ow;
        if (a < 1176)      { setting = 0; blk = a / 196; cell = a % 196; stride = 32;  size = 48;  ow = 14; }
        else if (a < 1470) { setting = 1; int r = a - 1176; blk = r / 49; cell = r % 49; stride = 64;  size = 96;  ow = 7; }
        else               { setting = 2; int r = a - 1470; blk = r / 16; cell = r % 16; stride = 128; size = 192; ow = 4; }
        int si = blk / 3, ai = blk % 3;
        double s;
        if (setting == 2) s = (si == 0) ? 1.0 : (si == 1) ? pow(2.0, 1.0/3.0) : pow(2.0, 2.0/3.0);
        else              s = (si == 0) ? pow(2.0, 1.0/3.0) : pow(2.0, 2.0/3.0);
        double ar = (ai == 0) ? 0.667 : (ai == 1) ? 1.0 : 1.5;
        float cyf = (float)(cell / ow) * (float)stride + (float)stride * 0.5f;
        float cxf = (float)(cell % ow) * (float)stride + (float)stride * 0.5f;
        double hh = (double)size * s / sqrt(ar);
        double ww = (double)size * s * sqrt(ar);
        double e0 = ((double)cyf - hh / 2.0) + 224.0;
        double e1 = ((double)cxf - ww / 2.0) + 224.0;
        double e2 = ((double)cyf + hh / 2.0) + 224.0;
        double e3 = ((double)cxf + ww / 2.0) + 224.0;
        int b0 = (int)e0, b1 = (int)e1, b2 = (int)e2, b3 = (int)e3;
        g_boxi[a*4+0] = b0; g_boxi[a*4+1] = b1; g_boxi[a*4+2] = b2; g_boxi[a*4+3] = b3;
        g_boxf[a*4+0] = (float)b0; g_boxf[a*4+1] = (float)b1;
        g_boxf[a*4+2] = (float)b2; g_boxf[a*4+3] = (float)b3;
    }

    if (idx < CSTEM * KP) {
        int m = idx / KP, k = idx % KP;
        float v = (k < KSTEM) ? sw[m * KSTEM + k] : 0.f;
        __nv_bfloat16 h = __float2bfloat16(v);
        g_Whi[idx] = h;
        g_Wlo[idx] = __float2bfloat16(v - __bfloat162float(h));
    }

    // d1w hi/lo split, 4 elements per thread (vectorized)
    if (idx < 128 * KD1 / 4) {
        float4 v = *(const float4*)&d1w[(size_t)idx * 4];
        uint16_t h0 = bf16_bits(v.x), h1 = bf16_bits(v.y);
        uint16_t h2 = bf16_bits(v.z), h3 = bf16_bits(v.w);
        float r0 = v.x - __bfloat162float(*(__nv_bfloat16*)&h0);
        float r1 = v.y - __bfloat162float(*(__nv_bfloat16*)&h1);
        float r2 = v.z - __bfloat162float(*(__nv_bfloat16*)&h2);
        float r3 = v.w - __bfloat162float(*(__nv_bfloat16*)&h3);
        uint16_t l0 = bf16_bits(r0), l1 = bf16_bits(r1);
        uint16_t l2 = bf16_bits(r2), l3 = bf16_bits(r3);
        uint2 hp = make_uint2((uint32_t)h0 | ((uint32_t)h1 << 16),
                              (uint32_t)h2 | ((uint32_t)h3 << 16));
        uint2 lp = make_uint2((uint32_t)l0 | ((uint32_t)l1 << 16),
                              (uint32_t)l2 | ((uint32_t)l3 << 16));
        *(uint2*)&g_d1whi[(size_t)idx * 4] = hp;
        *(uint2*)&g_d1wlo[(size_t)idx * 4] = lp;
    }

    if (idx < 32 * CSTEM) g_pfsum[idx] = 0.f;
    if (idx < BATCH * CSTEM) g_gsum[idx] = 0.f;
}

// im2col of x -> bf16 hi/lo, [n][KP] layout
__global__ void k_im2col_x(const float* __restrict__ x) {
    int idx = blockIdx.x * 256 + threadIdx.x;
    if (idx >= NXT * KP) return;
    int n = idx / KP, k = idx % KP;
    float v = 0.f;
    if (n < NX && k < KSTEM) {
        int b = n / NPOS, pos = n % NPOS, oy = pos / 14, ox = pos % 14;
        int c = k / 49, rr = k % 49, dy = rr / 7, dx = rr % 7;
        int iy = oy * 32 + dy - 3, ix = ox * 32 + dx - 3;
        if (iy >= 0 && ix >= 0)
            v = x[((b * 3 + c) * IMH + iy) * IMW + ix];
    }
    __nv_bfloat16 h = __float2bfloat16(v);
    g_Xhi[idx] = h;
    g_Xlo[idx] = __float2bfloat16(v - __bfloat162float(h));
}

// ---------------------------------------------------------------------------
// Shared mma tile geometry
// ---------------------------------------------------------------------------
#define KC      64
#define SSTR    72
#define TILE_E  (128 * SSTR)
#define SM_MMA_TOTAL (4 * TILE_E * 2)        // 73728 bytes

// ---------------------------------------------------------------------------
// Stem GEMM on mma.sync bf16x3: W[2048,KP] x X^T[KP,NX]
// Epilogue: bias+relu -> g_fhl (packed) + bucketed atomic global pooling.
// ---------------------------------------------------------------------------
__global__ void __launch_bounds__(256, 2) k_stem_gemm_mma(const float* __restrict__ Bias) {
    extern __shared__ __nv_bfloat16 smb[];
    __nv_bfloat16* Ah = smb;
    __nv_bfloat16* Al = smb + TILE_E;
    __nv_bfloat16* Bh = smb + 2 * TILE_E;
    __nv_bfloat16* Bl = smb + 3 * TILE_E;

    const int tid = threadIdx.x;
    const int wid = tid >> 5, lane = tid & 31;
    const int n0 = blockIdx.x * 128, m0 = blockIdx.y * 128;
    const int wm = (wid >> 2) * 64, wn = (wid & 3) * 32;
    const int g = lane >> 2, c2 = (lane & 3) * 2;

    float acc[4][4][4];
    #pragma unroll
    for (int i = 0; i < 4; i++)
        #pragma unroll
        for (int j = 0; j < 4; j++)
            #pragma unroll
            for (int r = 0; r < 4; r++) acc[i][j][r] = 0.f;

    for (int kc = 0; kc < KP; kc += KC) {
        __syncthreads();
        for (int idx = tid; idx < 1024; idx += 256) {
            int row = idx >> 3, c8 = (idx & 7) * 8;
            int so = row * SSTR + c8;
            size_t gA = (size_t)(m0 + row) * KP + kc + c8;
            size_t gB = (size_t)(n0 + row) * KP + kc + c8;
            cp_async16(&Ah[so], &g_Whi[gA]);
            cp_async16(&Al[so], &g_Wlo[gA]);
            cp_async16(&Bh[so], &g_Xhi[gB]);
            cp_async16(&Bl[so], &g_Xlo[gB]);
        }
        cp_async_wait_all();
        __syncthreads();

        #pragma unroll
        for (int ks = 0; ks < KC; ks += 16) {
            uint32_t ahi[4][4], alo[4][4], bhi[4][2], blo[4][2];
            #pragma unroll
            for (int i = 0; i < 4; i++) {
                int row = wm + i * 16 + g;
                int o0 = row * SSTR + ks + c2;
                int o1 = (row + 8) * SSTR + ks + c2;
                ahi[i][0] = *(const uint32_t*)&Ah[o0];
                ahi[i][1] = *(const uint32_t*)&Ah[o1];
                ahi[i][2] = *(const uint32_t*)&Ah[o0 + 8];
                ahi[i][3] = *(const uint32_t*)&Ah[o1 + 8];
                alo[i][0] = *(const uint32_t*)&Al[o0];
                alo[i][1] = *(const uint32_t*)&Al[o1];
                alo[i][2] = *(const uint32_t*)&Al[o0 + 8];
                alo[i][3] = *(const uint32_t*)&Al[o1 + 8];
            }
            #pragma unroll
            for (int j = 0; j < 4; j++) {
                int col = wn + j * 8 + g;
                int o = col * SSTR + ks + c2;
                bhi[j][0] = *(const uint32_t*)&Bh[o];
                bhi[j][1] = *(const uint32_t*)&Bh[o + 8];
                blo[j][0] = *(const uint32_t*)&Bl[o];
                blo[j][1] = *(const uint32_t*)&Bl[o + 8];
            }
            #pragma unroll
            for (int i = 0; i < 4; i++)
                #pragma unroll
                for (int j = 0; j < 4; j++) {
                    mma_bf16(acc[i][j], ahi[i], bhi[j]);
                    mma_bf16(acc[i][j], ahi[i], blo[j]);
                    mma_bf16(acc[i][j], alo[i], bhi[j]);
                }
        }
    }

    // epilogue: bias+relu -> packed g_fhl, bucketed atomic pooling into g_gsum
    #pragma unroll
    for (int i = 0; i < 4; i++) {
        #pragma unroll
        for (int half = 0; half < 2; half++) {
            int m = m0 + wm + i * 16 + g + half * 8;
            float bias = Bias[m];
            int pb = -1; float sum = 0.f;
            #pragma unroll
            for (int j = 0; j < 4; j++) {
                #pragma unroll
                for (int e = 0; e < 2; e++) {
                    int n = n0 + wn + j * 8 + c2 + e;
                    if (n < NX) {
                        float v = fmaxf(acc[i][j][half * 2 + e] + bias, 0.f);
                        int b = n / NPOS, pos = n % NPOS;
                        g_fhl[((size_t)(b * CSTEM + m)) * NPOS + pos] = pack_hilo(v);
                        if (b != pb) {
                            if (pb >= 0) atomicAdd(&g_gsum[pb * CSTEM + m], sum);
                            sum = 0.f; pb = b;
                        }
                        sum += v;
                    }
                }
            }
            if (pb >= 0) atomicAdd(&g_gsum[pb * CSTEM + m], sum);
        }
    }
}

// ---------------------------------------------------------------------------
// down1 GEMM on mma.sync bf16x3 (B gathered implicitly from packed g_fhl).
// A tiles prefetched via cp.async, overlapped with the B gather phase.
// ---------------------------------------------------------------------------
__global__ void __launch_bounds__(256, 2) k_d1_gemm_mma() {
    extern __shared__ __nv_bfloat16 smb[];
    __nv_bfloat16* Ah = smb;
    __nv_bfloat16* Al = smb + TILE_E;
    __nv_bfloat16* Bh = smb + 2 * TILE_E;
    __nv_bfloat16* Bl = smb + 3 * TILE_E;

    const int tid = threadIdx.x;
    const int wid = tid >> 5, lane = tid & 31;
    const int n0 = blockIdx.x * 128;
    const int kStart = blockIdx.y * (KD1 / NSPLIT);
    const int wm = (wid >> 2) * 64, wn = (wid & 3) * 32;
    const int g = lane >> 2, c2 = (lane & 3) * 2;

    const int bcol = tid & 127;
    const int kh = tid >> 7;         // 0 or 1: which 32-k half
    const int nB = n0 + bcol;
    const bool bval = nB < NX;
    int bb = 0, boy = 0, box = 0;
    if (bval) { bb = nB / NPOS; int pos = nB % NPOS; boy = pos / 14; box = pos % 14; }

    float acc[4][4][4];
    #pragma unroll
    for (int i = 0; i < 4; i++)
        #pragma unroll
        for (int j = 0; j < 4; j++)
            #pragma unroll
            for (int r = 0; r < 4; r++) acc[i][j][r] = 0.f;

    for (int kc = 0; kc < KD1 / NSPLIT; kc += KC) {
        int k0 = kStart + kc;
        __syncthreads();
        // A: cp.async copies (in flight during the B gather below)
        for (int idx = tid; idx < 1024; idx += 256) {
            int row = idx >> 3, c8 = (idx & 7) * 8;
            int so = row * SSTR + c8;
            size_t gA = (size_t)row * KD1 + k0 + c8;
            cp_async16(&Ah[so], &g_d1whi[gA]);
            cp_async16(&Al[so], &g_d1wlo[gA]);
        }
        // B: implicit im2col gather, 2 k per u32 store
        #pragma unroll 4
        for (int kk = kh * 32; kk < kh * 32 + 32; kk += 2) {
            int k = k0 + kk;
            int c0 = k / 9, t90 = k - 9 * c0;
            int iy0 = boy + t90 / 3 - 1, ix0 = box + (t90 - 3 * (t90 / 3)) - 1;
            uint32_t v0 = 0;
            if (bval && (unsigned)iy0 < 14u && (unsigned)ix0 < 14u)
                v0 = g_fhl[((size_t)(bb * CSTEM + c0)) * NPOS + iy0 * 14 + ix0];
            int k1 = k + 1;
            int c1 = k1 / 9, t91 = k1 - 9 * c1;
            int iy1 = boy + t91 / 3 - 1, ix1 = box + (t91 - 3 * (t91 / 3)) - 1;
            uint32_t v1 = 0;
            if (bval && (unsigned)iy1 < 14u && (unsigned)ix1 < 14u)
                v1 = g_fhl[((size_t)(bb * CSTEM + c1)) * NPOS + iy1 * 14 + ix1];
            int so = bcol * SSTR + kk;   // even offset -> u32-aligned
            *(uint32_t*)&Bh[so] = (v0 & 0xFFFFu) | ((v1 & 0xFFFFu) << 16);
            *(uint32_t*)&Bl[so] = (v0 >> 16) | (v1 & 0xFFFF0000u);
        }
        cp_async_wait_all();
        __syncthreads();

        #pragma unroll
        for (int ks = 0; ks < KC; ks += 16) {
            uint32_t ahi[4][4], alo[4][4], bhi[4][2], blo[4][2];
            #pragma unroll
            for (int i = 0; i < 4; i++) {
                int row = wm + i * 16 + g;
                int o0 = row * SSTR + ks + c2;
                int o1 = (row + 8) * SSTR + ks + c2;
                ahi[i][0] = *(const uint32_t*)&Ah[o0];
                ahi[i][1] = *(const uint32_t*)&Ah[o1];
                ahi[i][2] = *(const uint32_t*)&Ah[o0 + 8];
                ahi[i][3] = *(const uint32_t*)&Ah[o1 + 8];
                alo[i][0] = *(const uint32_t*)&Al[o0];
                alo[i][1] = *(const uint32_t*)&Al[o1];
                alo[i][2] = *(const uint32_t*)&Al[o0 + 8];
                alo[i][3] = *(const uint32_t*)&Al[o1 + 8];
            }
            #pragma unroll
            for (int j = 0; j < 4; j++) {
                int col = wn + j * 8 + g;
                int o = col * SSTR + ks + c2;
                bhi[j][0] = *(const uint32_t*)&Bh[o];
                bhi[j][1] = *(const uint32_t*)&Bh[o + 8];
                blo[j][0] = *(const uint32_t*)&Bl[o];
                blo[j][1] = *(const uint32_t*)&Bl[o + 8];
            }
            #pragma unroll
            for (int i = 0; i < 4; i++)
                #pragma unroll
                for (int j = 0; j < 4; j++) {
                    mma_bf16(acc[i][j], ahi[i], bhi[j]);
                    mma_bf16(acc[i][j], ahi[i], blo[j]);
                    mma_bf16(acc[i][j], alo[i], bhi[j]);
                }
        }
    }

    float* C = g_partials + (size_t)blockIdx.y * 128 * ND1;
    #pragma unroll
    for (int i = 0; i < 4; i++) {
        #pragma unroll
        for (int half = 0; half < 2; half++) {
            int m = wm + i * 16 + g + half * 8;
            #pragma unroll
            for (int j = 0; j < 4; j++) {
                int n = n0 + wn + j * 8 + c2;
                *(float2*)(C + (size_t)m * ND1 + n) =
                    make_float2(acc[i][j][half * 2], acc[i][j][half * 2 + 1]);
            }
        }
    }
}

// ---------------------------------------------------------------------------
// Part-stem GEMM on mma.sync bf16x3 (2 CTAs/SM, cp.async loader)
// ---------------------------------------------------------------------------
__global__ void __launch_bounds__(256, 2) k_part_gemm_mma(const float* __restrict__ Bias) {
    extern __shared__ __nv_bfloat16 smb[];
    __nv_bfloat16* Ah = smb;
    __nv_bfloat16* Al = smb + TILE_E;
    __nv_bfloat16* Bh = smb + 2 * TILE_E;
    __nv_bfloat16* Bl = smb + 3 * TILE_E;

    const int tid = threadIdx.x;
    const int wid = tid >> 5, lane = tid & 31;
    const int n0 = blockIdx.x * 128, m0 = blockIdx.y * 128;
    const int wm = (wid >> 2) * 64, wn = (wid & 3) * 32;
    const int g = lane >> 2, c2 = (lane & 3) * 2;

    float acc[4][4][4];
    #pragma unroll
    for (int i = 0; i < 4; i++)
        #pragma unroll
        for (int j = 0; j < 4; j++)
            #pragma unroll
            for (int r = 0; r < 4; r++) acc[i][j][r] = 0.f;

    for (int kc = 0; kc < KP; kc += KC) {
        __syncthreads();
        for (int idx = tid; idx < 1024; idx += 256) {
            int row = idx >> 3, c8 = (idx & 7) * 8;
            int so = row * SSTR + c8;
            size_t gA = (size_t)(m0 + row) * KP + kc + c8;
            size_t gB = (size_t)(n0 + row) * KP + kc + c8;
            cp_async16(&Ah[so], &g_Whi[gA]);
            cp_async16(&Al[so], &g_Wlo[gA]);
            cp_async16(&Bh[so], &g_Phi[gB]);
            cp_async16(&Bl[so], &g_Plo[gB]);
        }
        cp_async_wait_all();
        __syncthreads();

        #pragma unroll
        for (int ks = 0; ks < KC; ks += 16) {
            uint32_t ahi[4][4], alo[4][4], bhi[4][2], blo[4][2];
            #pragma unroll
            for (int i = 0; i < 4; i++) {
                int row = wm + i * 16 + g;
                int o0 = row * SSTR + ks + c2;
                int o1 = (row + 8) * SSTR + ks + c2;
                ahi[i][0] = *(const uint32_t*)&Ah[o0];
                ahi[i][1] = *(const uint32_t*)&Ah[o1];
                ahi[i][2] = *(const uint32_t*)&Ah[o0 + 8];
                ahi[i][3] = *(const uint32_t*)&Ah[o1 + 8];
                alo[i][0] = *(const uint32_t*)&Al[o0];
                alo[i][1] = *(const uint32_t*)&Al[o1];
                alo[i][2] = *(const uint32_t*)&Al[o0 + 8];
                alo[i][3] = *(const uint32_t*)&Al[o1 + 8];
            }
            #pragma unroll
            for (int j = 0; j < 4; j++) {
                int col = wn + j * 8 + g;
                int o = col * SSTR + ks + c2;
                bhi[j][0] = *(const uint32_t*)&Bh[o];
                bhi[j][1] = *(const uint32_t*)&Bh[o + 8];
                blo[j][0] = *(const uint32_t*)&Bl[o];
                blo[j][1] = *(const uint32_t*)&Bl[o + 8];
            }
            #pragma unroll
            for (int i = 0; i < 4; i++)
                #pragma unroll
                for (int j = 0; j < 4; j++) {
                    mma_bf16(acc[i][j], ahi[i], bhi[j]);
                    mma_bf16(acc[i][j], ahi[i], blo[j]);
                    mma_bf16(acc[i][j], alo[i], bhi[j]);
                }
        }
    }

    #pragma unroll
    for (int i = 0; i < 4; i++) {
        #pragma unroll
        for (int half = 0; half < 2; half++) {
            int m = m0 + wm + i * 16 + g + half * 8;
            float bias = Bias[m];
            int pb = -1; float sum = 0.f;
            #pragma unroll
            for (int j = 0; j < 4; j++) {
                #pragma unroll
                for (int e = 0; e < 2; e++) {
                    int n = n0 + wn + j * 8 + c2 + e;
                    float v = fmaxf(acc[i][j][half * 2 + e] + bias, 0.f);
                    int p = n / NPOS;
                    if (p != pb) {
                        if (pb >= 0) atomicAdd(&g_pfsum[pb * CSTEM + m], sum);
                        sum = 0.f; pb = p;
                    }
                    sum += v;
                }
            }
            atomicAdd(&g_pfsum[pb * CSTEM + m], sum);
        }
    }
}

// ---------------------------------------------------------------------------
// Epilogues / small stages
// ---------------------------------------------------------------------------
__global__ void k_raw_logits(const float* __restrict__ fcw, const float* __restrict__ fcb,
                             float* __restrict__ out) {
    int w = blockIdx.x * 8 + (threadIdx.x >> 5);
    int lane = threadIdx.x & 31;
    if (w >= BATCH * CAT) return;
    int b = w / CAT, j = w % CAT;
    const float* gv = g_gsum + b * CSTEM;
    const float* wv = fcw + (size_t)j * CSTEM;
    float s = 0.f;
    for (int k = lane; k < CSTEM; k += 32) s += gv[k] * wv[k];
    s = warp_red(s);
    if (!lane) out[w] = s / 196.0f + fcb[j];
}

// vectorized split-K reduce: 4 consecutive n per thread (float4)
__global__ void k_reduce_d1(const float* __restrict__ d1b) {
    int idx = blockIdx.x * 256 + threadIdx.x;
    if (idx >= BATCH * 128 * NPOS / 4) return;
    int q = idx * 4;
    int b = q / (128 * NPOS), r = q % (128 * NPOS);
    int c = r / NPOS, p = r % NPOS;          // p multiple of 4 (196 % 4 == 0)
    int n = b * NPOS + p;
    float4 s = make_float4(0.f, 0.f, 0.f, 0.f);
    #pragma unroll
    for (int z = 0; z < NSPLIT; z++) {
        float4 v = *(const float4*)&g_partials[(size_t)(z * 128 + c) * ND1 + n];
        s.x += v.x; s.y += v.y; s.z += v.z; s.w += v.w;
    }
    float bias = d1b[c];
    *(float4*)&g_d1[q] = make_float4(fmaxf(s.x + bias, 0.f), fmaxf(s.y + bias, 0.f),
                                     fmaxf(s.z + bias, 0.f), fmaxf(s.w + bias, 0.f));
}

__global__ void k_down2(const float* __restrict__ w2, const float* __restrict__ b2) {
    int w = blockIdx.x * 8 + (threadIdx.x >> 5);
    int lane = threadIdx.x & 31;
    if (w >= BATCH * 128 * 49) return;
    int b = w / (128 * 49), r = w % (128 * 49);
    int oc = r / 49, pos = r % 49, oy = pos / 7, ox = pos % 7;
    float s = 0.f;
    for (int ic = lane; ic < 128; ic += 32) {
        const float* dp = g_d1 + (size_t)(b * 128 + ic) * NPOS;
        const float* wp = w2 + (size_t)(oc * 128 + ic) * 9;
        #pragma unroll
        for (int ky = 0; ky < 3; ky++) {
            int iy = oy * 2 + ky - 1;
            if ((unsigned)iy >= 14u) continue;
            #pragma unroll
            for (int kx = 0; kx < 3; kx++) {
                int ix = ox * 2 + kx - 1;
                if ((unsigned)ix < 14u) s += wp[ky * 3 + kx] * dp[iy * 14 + ix];
            }
        }
    }
    s = warp_red(s);
    if (!lane) g_d2[w] = fmaxf(s + b2[oc], 0.f);
}

__global__ void k_down3(const float* __restrict__ w3, const float* __restrict__ b3) {
    int w = blockIdx.x * 8 + (threadIdx.x >> 5);
    int lane = threadIdx.x & 31;
    if (w >= BATCH * 128 * 16) return;
    int b = w / (128 * 16), r = w % (128 * 16);
    int oc = r / 16, pos = r % 16, oy = pos / 4, ox = pos % 4;
    float s = 0.f;
    for (int ic = lane; ic < 128; ic += 32) {
        const float* dp = g_d2 + (size_t)(b * 128 + ic) * 49;
        const float* wp = w3 + (size_t)(oc * 128 + ic) * 9;
        #pragma unroll
        for (int ky = 0; ky < 3; ky++) {
            int iy = oy * 2 + ky - 1;
            if ((unsigned)iy >= 7u) continue;
            #pragma unroll
            for (int kx = 0; kx < 3; kx++) {
                int ix = ox * 2 + kx - 1;
                if ((unsigned)ix < 7u) s += wp[ky * 3 + kx] * dp[iy * 7 + ix];
            }
        }
    }
    s = warp_red(s);
    if (!lane) g_d3[w] = fmaxf(s + b3[oc], 0.f);
}

__global__ void k_tidy(const float* __restrict__ w1, const float* __restrict__ b1,
                       const float* __restrict__ w2, const float* __restrict__ b2,
                       const float* __restrict__ w3, const float* __restrict__ b3) {
    int w = blockIdx.x * 8 + (threadIdx.x >> 5);
    int lane = threadIdx.x & 31;
    if (w >= BATCH * NANCH) return;
    int b = w / NANCH, o = w % NANCH;
    const float* src; const float* wt; float bias; int S;
    if (o < 1176)      { int oc = o / 196, pos = o % 196; src = g_d1 + (size_t)b * 128 * 196 + pos; S = 196; wt = w1 + oc * 128; bias = b1[oc]; }
    else if (o < 1470) { int r = o - 1176, oc = r / 49, pos = r % 49; src = g_d2 + (size_t)b * 128 * 49 + pos; S = 49; wt = w2 + oc * 128; bias = b2[oc]; }
    else               { int r = o - 1470, oc = r / 16, pos = r % 16; src = g_d3 + (size_t)b * 128 * 16 + pos; S = 16; wt = w3 + oc * 128; bias = b3[oc]; }
    float s = 0.f;
    for (int ic = lane; ic < 128; ic += 32) s += wt[ic] * src[ic * S];
    s = warp_red(s);
    if (!lane) g_scores[b * NANCH + o] = s + bias;
}

// ---------------------------------------------------------------------------
// NMS (one block per image, matches jnp.argmax first-max tie-break)
// ---------------------------------------------------------------------------
__global__ void k_nms() {
    __shared__ float sm[NANCH];
    __shared__ float rv[256];
    __shared__ int   ri[256];
    int b = blockIdx.x, tid = threadIdx.x;
    for (int i = tid; i < NANCH; i += 256) sm[i] = g_scores[b * NANCH + i];
    __syncthreads();
    for (int t = 0; t < 4; t++) {
        float bv = neg_inf(); int bi = 0x3fffffff;
        for (int i = tid; i < NANCH; i += 256) {
            float v = sm[i];
            if (v > bv || (v == bv && i < bi)) { bv = v; bi = i; }
        }
        rv[tid] = bv; ri[tid] = bi;
        __syncthreads();
        for (int s = 128; s > 0; s >>= 1) {
            if (tid < s) {
                float v2 = rv[tid + s]; int i2 = ri[tid + s];
                if (v2 > rv[tid] || (v2 == rv[tid] && i2 < ri[tid])) { rv[tid] = v2; ri[tid] = i2; }
            }
            __syncthreads();
        }
        int pick = ri[0];
        if (tid == 0) {
            g_pick[b * 4 + t] = pick;
            g_prob[b * 4 + t] = g_scores[b * NANCH + pick];
            int y0 = g_boxi[pick * 4 + 0], x0 = g_boxi[pick * 4 + 1];
            int y1 = max(g_boxi[pick * 4 + 2], y0 + 1);
            int x1 = max(g_boxi[pick * 4 + 3], x0 + 1);
            int pi = b * 4 + t;
            g_cropi[pi * 4 + 0] = y0; g_cropi[pi * 4 + 1] = x0;
            g_cropi[pi * 4 + 2] = y1 - 1; g_cropi[pi * 4 + 3] = x1 - 1;
            g_cropf[pi * 4 + 0] = (float)y0;
            g_cropf[pi * 4 + 1] = __fdiv_rn((float)(y1 - 1 - y0), 447.0f);
            g_cropf[pi * 4 + 2] = (float)x0;
            g_cropf[pi * 4 + 3] = __fdiv_rn((float)(x1 - 1 - x0), 447.0f);
        }
        __syncthreads();
        float py0 = g_boxf[pick * 4], px0 = g_boxf[pick * 4 + 1];
        float py1 = g_boxf[pick * 4 + 2], px1 = g_boxf[pick * 4 + 3];
        float pa = (py1 - py0) * (px1 - px0);
        for (int i = tid; i < NANCH; i += 256) {
            float qy0 = g_boxf[i * 4], qx0 = g_boxf[i * 4 + 1];
            float qy1 = g_boxf[i * 4 + 2], qx1 = g_boxf[i * 4 + 3];
            float t0 = fmaxf(qy0, py0), t1 = fmaxf(qx0, px0);
            float bb0 = fminf(qy1, py1), bb1 = fminf(qx1, px1);
            float w0 = bb0 - t0, w1 = bb1 - t1;
            float inter = (w0 < 0.f || w1 < 0.f) ? 0.f : w0 * w1;
            float qa = (qy1 - qy0) * (qx1 - qx0);
            float iou = inter / (qa + pa - inter);
            if (!(iou < 0.25f)) sm[i] = neg_inf();
        }
        __syncthreads();
    }
}

// ---------------------------------------------------------------------------
// Fused crop-resize + im2col for part stem -> bf16 hi/lo [n][KP]
// ---------------------------------------------------------------------------
__global__ void k_part_im2col(const float* __restrict__ x) {
    int idx = blockIdx.x * 256 + threadIdx.x;
    if (idx >= NPART * KP) return;
    int col = idx / KP, r = idx % KP;
    float v = 0.f;
    if (r < KSTEM) {
        int p = col / NPOS, pos = col % NPOS, oy = pos / 14, ox = pos % 14;
        int c = r / 49, rr = r % 49, dy = rr / 7, dx = rr % 7;
        int iy = oy * 32 + dy - 3, ix = ox * 32 + dx - 3;
        if (iy >= 0 && ix >= 0) {
            int b = p >> 2;
            float y0f = g_cropf[p * 4 + 0], sy = g_cropf[p * 4 + 1];
            float x0f = g_cropf[p * 4 + 2], sx = g_cropf[p * 4 + 3];
            int y1m1 = g_cropi[p * 4 + 2], x1m1 = g_cropi[p * 4 + 3];
            float fy = __fadd_rn(y0f, __fmul_rn((float)iy, sy));
            int yl = (int)floorf(fy);
            float wy = __fsub_rn(fy, (float)yl);
            int yh = min(yl + 1, y1m1);
            float fx = __fadd_rn(x0f, __fmul_rn((float)ix, sx));
            int xl = (int)floorf(fx);
            float wx = __fsub_rn(fx, (float)xl);
            int xh = min(xl + 1, x1m1);
            const float* xb = x + (size_t)(b * 3 + c) * IMH * IMW;
            int ry0 = yl - 224, ry1 = yh - 224, rx0 = xl - 224, rx1 = xh - 224;
            float vll = ((unsigned)ry0 < 448u && (unsigned)rx0 < 448u) ? xb[ry0 * IMW + rx0] : 0.f;
            float vlh = ((unsigned)ry0 < 448u && (unsigned)rx1 < 448u) ? xb[ry0 * IMW + rx1] : 0.f;
            float vhl = ((unsigned)ry1 < 448u && (unsigned)rx0 < 448u) ? xb[ry1 * IMW + rx0] : 0.f;
            float vhh = ((unsigned)ry1 < 448u && (unsigned)rx1 < 448u) ? xb[ry1 * IMW + rx1] : 0.f;
            float omy = __fsub_rn(1.f, wy), omx = __fsub_rn(1.f, wx);
            float top = __fadd_rn(__fmul_rn(omx, vll), __fmul_rn(wx, vlh));
            float bot = __fadd_rn(__fmul_rn(omx, vhl), __fmul_rn(wx, vhh));
            v = __fadd_rn(__fmul_rn(omy, top), __fmul_rn(wy, bot));
        }
    }
    __nv_bfloat16 h = __float2bfloat16(v);
    g_Phi[idx] = h;
    g_Plo[idx] = __float2bfloat16(v - __bfloat162float(h));
}

__global__ void k_fc_concat(const float* __restrict__ cw, const float* __restrict__ cb,
                            float* __restrict__ out) {
    int w = blockIdx.x * 8 + (threadIdx.x >> 5);
    int lane = threadIdx.x & 31;
    if (w >= BATCH * CAT) return;
    int b = w / CAT, j = w % CAT;
    const float* wv = cw + (size_t)j * 10240;
    const float* pfs = g_pfsum + (size_t)b * 4 * CSTEM;
    float s = 0.f;
    for (int k = lane; k < 8192; k += 32) s += pfs[k] * wv[k];
    const float* gv = g_gsum + b * CSTEM;
    for (int k = lane; k < 2048; k += 32) s += gv[k] * wv[8192 + k];
    s = warp_red(s);
    if (!lane) out[1600 + w] = s / 196.0f + cb[j];
}

// part logits + pick/prob tail (fused)
__global__ void k_fc_part(const float* __restrict__ pw, const float* __restrict__ pb,
                          float* __restrict__ out) {
    int w = blockIdx.x * 8 + (threadIdx.x >> 5);
    int lane = threadIdx.x & 31;
    if (blockIdx.x == 0 && threadIdx.x < 32) {
        out[9600 + threadIdx.x] = (float)g_pick[threadIdx.x];
        out[9632 + threadIdx.x] = g_prob[threadIdx.x];
    }
    if (w >= 32 * CAT) return;
    int p = w / CAT, j = w % CAT;
    const float* av = g_pfsum + (size_t)p * CSTEM;
    const float* wv = pw + (size_t)j * CSTEM;
    float s = 0.f;
    for (int k = lane; k < CSTEM; k += 32) s += av[k] * wv[k];
    s = warp_red(s / 196.0f);
    if (!lane) out[3200 + w] = s + pb[j];
}

// ---------------------------------------------------------------------------
// Launch
// ---------------------------------------------------------------------------
extern "C" void kernel_launch(void* const* d_in, const int* in_sizes, int n_in,
                              void* d_out, int out_size) {
    (void)in_sizes; (void)n_in; (void)out_size;
    const float* x      = (const float*)d_in[0];
    const float* stem_w = (const float*)d_in[1];
    const float* stem_b = (const float*)d_in[2];
    const float* fc_w   = (const float*)d_in[3];
    const float* fc_b   = (const float*)d_in[4];
    const float* d1w    = (const float*)d_in[5];
    const float* d1b    = (const float*)d_in[6];
    const float* d2w    = (const float*)d_in[7];
    const float* d2b    = (const float*)d_in[8];
    const float* d3w    = (const float*)d_in[9];
    const float* d3b    = (const float*)d_in[10];
    const float* t1w    = (const float*)d_in[11];
    const float* t1b    = (const float*)d_in[12];
    const float* t2w    = (const float*)d_in[13];
    const float* t2b    = (const float*)d_in[14];
    const float* t3w    = (const float*)d_in[15];
    const float* t3b    = (const float*)d_in[16];
    const float* cw     = (const float*)d_in[17];
    const float* cb     = (const float*)d_in[18];
    const float* pw     = (const float*)d_in[19];
    const float* pb     = (const float*)d_in[20];
    float* out = (float*)d_out;

    cudaFuncSetAttribute(k_stem_gemm_mma, cudaFuncAttributeMaxDynamicSharedMemorySize,
                         SM_MMA_TOTAL);
    cudaFuncSetAttribute(k_d1_gemm_mma, cudaFuncAttributeMaxDynamicSharedMemorySize,
                         SM_MMA_TOTAL);
    cudaFuncSetAttribute(k_part_gemm_mma, cudaFuncAttributeMaxDynamicSharedMemorySize,
                         SM_MMA_TOTAL);

    // prep: anchors + weight hi/lo splits (vectorized d1w) + accumulator zeroing
    k_prep<<<GRID_PREP, 256>>>(stem_w, d1w);

    // --- backbone on x: tensor-core stem GEMM (fused relu+pack+pool) ---
    k_im2col_x<<<(NXT * KP + 255) / 256, 256>>>(x);
    k_stem_gemm_mma<<<dim3(NXT / 128, CSTEM / 128), 256, SM_MMA_TOTAL>>>(stem_b);
    k_raw_logits<<<(BATCH * CAT) / 8, 256>>>(fc_w, fc_b, out);

    // --- proposal net: tensor-core d1 GEMM (implicit im2col gather) ---
    k_d1_gemm_mma<<<dim3(ND1 / 128, NSPLIT), 256, SM_MMA_TOTAL>>>();
    k_reduce_d1<<<(BATCH * 128 * NPOS / 4 + 255) / 256, 256>>>(d1b);
    k_down2<<<(BATCH * 128 * 49 + 7) / 8, 256>>>(d2w, d2b);
    k_down3<<<(BATCH * 128 * 16 + 7) / 8, 256>>>(d3w, d3b);
    k_tidy<<<(BATCH * NANCH + 7) / 8, 256>>>(t1w, t1b, t2w, t2b, t3w, t3b);

    // --- NMS ---
    k_nms<<<8, 256>>>();

    // --- part branch: crop-resize im2col (bf16 hi/lo) + mma.sync GEMM ---
    k_part_im2col<<<(NPART * KP + 255) / 256, 256>>>(x);
    k_part_gemm_mma<<<dim3(NPART / 128, CSTEM / 128), 256, SM_MMA_TOTAL>>>(stem_b);

    // --- heads ---
    k_fc_concat<<<(BATCH * CAT) / 8, 256>>>(cw, cb, out);
    k_fc_part<<<(32 * CAT) / 8, 256>>>(pw, pb, out);
}